// round 1
// baseline (speedup 1.0000x reference)
#include <cuda_runtime.h>
#include <stdint.h>
#include <math.h>

#define NN 100000
#define NE 3200000

// ---------------- scratch (device globals: no allocation allowed) ----------
__device__ float g_deg[NN];
__device__ float g_dinv[NN];
__device__ float g_h1s[NN * 16];   // (x@W1) * dinv[row]
__device__ float g_acc1[NN * 16];  // scatter accumulator, layer 1
__device__ float g_h2s[NN * 8];    // (relu-out @ W2) * dinv[row], padded to 8
__device__ float g_acc2[NN * 8];   // scatter accumulator, layer 2 (padded)
__device__ int   g_is64;           // edge_index dtype flag

// vector reduction (sm_90+): 4-float global atomic add, no return
__device__ __forceinline__ void red4(float* p, float4 v) {
    asm volatile("red.global.add.v4.f32 [%0], {%1,%2,%3,%4};"
                 :: "l"(p), "f"(v.x), "f"(v.y), "f"(v.z), "f"(v.w) : "memory");
}

// ---------------- dtype detection -----------------------------------------
// int64 little-endian: every odd 32-bit word (high half) is 0 (ids < 2^31).
// int32: odd words are random node ids in [0,100000) — all-zero is impossible.
__global__ void detect_kernel(const unsigned* __restrict__ ei) {
    __shared__ int nz;
    int tid = threadIdx.x;
    if (tid == 0) nz = 0;
    __syncthreads();
    unsigned v = 0;
#pragma unroll
    for (int i = 0; i < 16; i++) v |= ei[2 * (tid * 16 + i) + 1];
    if (v) nz = 1;
    __syncthreads();
    if (tid == 0) g_is64 = (nz == 0) ? 1 : 0;
}

// ---------------- degree + normalization ----------------------------------
__global__ __launch_bounds__(256) void deg_kernel(const void* __restrict__ ei) {
    int e = blockIdx.x * 256 + threadIdx.x;
    if (e >= NE) return;
    int d;
    if (g_is64) d = (int)__ldg(((const long long*)ei) + NE + e);
    else        d = __ldg(((const int*)ei) + NE + e);
    atomicAdd(&g_deg[d], 1.0f);
}

__global__ __launch_bounds__(256) void dinv_kernel() {
    int i = blockIdx.x * 256 + threadIdx.x;
    if (i < NN) g_dinv[i] = rsqrtf(g_deg[i] + 1.0f);  // +1 = self loop
}

// ---------------- GEMM1: h1s = (x @ W1) * dinv ----------------------------
// block = 256 threads, tile = 32 rows x 512 k x 16 j.
// lane layout: warp w -> rows 4w..4w+3 ; r = 4w + (lane>>3), jp = lane&7
// (j pair 2jp,2jp+1). Packed dual-FP32 FMA via fma.rn.f32x2.
#define XS_STRIDE 520
__global__ __launch_bounds__(256) void gemm1_kernel(const float* __restrict__ x,
                                                    const float* __restrict__ W1) {
    extern __shared__ float smem[];
    float* xs = smem;                    // 32 * 520 floats
    float* ws = smem + 32 * XS_STRIDE;   // 512 * 16 floats
    int tid = threadIdx.x;
    int row0 = blockIdx.x * 32;

    // load W1 (8192 floats = 2048 float4)
    {
        const float4* Wv = (const float4*)W1;
        float4* wsv = (float4*)ws;
#pragma unroll
        for (int i = 0; i < 8; i++) wsv[tid + 256 * i] = Wv[tid + 256 * i];
    }
    // load x tile (32 rows x 512 = 4096 float4), coalesced
    {
        const float4* xv = (const float4*)x;
#pragma unroll
        for (int i = 0; i < 16; i++) {
            int idx = tid + 256 * i;
            int r = idx >> 7, c4 = idx & 127;
            float4 v = xv[(long)(row0 + r) * 128 + c4];
            *(float4*)(xs + r * XS_STRIDE + 4 * c4) = v;
        }
    }
    __syncthreads();

    int lane = tid & 31, warp = tid >> 5;
    int r  = warp * 4 + (lane >> 3);
    int jp = lane & 7;
    const float* xrow = xs + r * XS_STRIDE;
    const float* wp = ws + 2 * jp;

    unsigned long long acc = 0ULL;  // packed (0.0f, 0.0f)
#pragma unroll 2
    for (int k = 0; k < 512; k += 4) {
        float4 xv = *(const float4*)(xrow + k);
        unsigned long long x0, x1, x2, x3, w0, w1, w2, w3;
        asm("mov.b64 %0,{%1,%1};" : "=l"(x0) : "f"(xv.x));
        asm("mov.b64 %0,{%1,%1};" : "=l"(x1) : "f"(xv.y));
        asm("mov.b64 %0,{%1,%1};" : "=l"(x2) : "f"(xv.z));
        asm("mov.b64 %0,{%1,%1};" : "=l"(x3) : "f"(xv.w));
        w0 = *(const unsigned long long*)(wp + (k + 0) * 16);
        w1 = *(const unsigned long long*)(wp + (k + 1) * 16);
        w2 = *(const unsigned long long*)(wp + (k + 2) * 16);
        w3 = *(const unsigned long long*)(wp + (k + 3) * 16);
        asm("fma.rn.f32x2 %0, %1, %2, %0;" : "+l"(acc) : "l"(x0), "l"(w0));
        asm("fma.rn.f32x2 %0, %1, %2, %0;" : "+l"(acc) : "l"(x1), "l"(w1));
        asm("fma.rn.f32x2 %0, %1, %2, %0;" : "+l"(acc) : "l"(x2), "l"(w2));
        asm("fma.rn.f32x2 %0, %1, %2, %0;" : "+l"(acc) : "l"(x3), "l"(w3));
    }
    float a0, a1;
    asm("mov.b64 {%0,%1}, %2;" : "=f"(a0), "=f"(a1) : "l"(acc));
    int grow = row0 + r;
    float di = g_dinv[grow];
    *(float2*)(g_h1s + (long)grow * 16 + 2 * jp) = make_float2(a0 * di, a1 * di);
}

// ---------------- layer-1 scatter: acc1[dst] += h1s[src] ------------------
__global__ __launch_bounds__(256) void scatter1_kernel(const void* __restrict__ ei) {
    int e = blockIdx.x * 256 + threadIdx.x;
    if (e >= NE) return;
    int s, d;
    if (g_is64) {
        const long long* p = (const long long*)ei;
        s = (int)__ldg(p + e); d = (int)__ldg(p + NE + e);
    } else {
        const int* p = (const int*)ei;
        s = __ldg(p + e); d = __ldg(p + NE + e);
    }
    const float4* hv = (const float4*)(g_h1s + (long)s * 16);
    float4 v0 = __ldg(hv + 0), v1 = __ldg(hv + 1), v2 = __ldg(hv + 2), v3 = __ldg(hv + 3);
    float* b = g_acc1 + (long)d * 16;
    red4(b, v0); red4(b + 4, v1); red4(b + 8, v2); red4(b + 12, v3);
}

// ---------------- post1: relu(dinv*(acc1+h1s)+b1) @ W2, *dinv -> h2s -------
__global__ __launch_bounds__(256) void post1_kernel(const float* __restrict__ b1,
                                                    const float* __restrict__ W2) {
    __shared__ float w2s[112];
    __shared__ float b1s[16];
    int tid = threadIdx.x;
    if (tid < 112) w2s[tid] = W2[tid];
    if (tid < 16)  b1s[tid] = b1[tid];
    __syncthreads();
    int i = blockIdx.x * 256 + tid;
    if (i >= NN) return;
    float di = g_dinv[i];
    const float4* av = (const float4*)(g_acc1 + (long)i * 16);
    const float4* hv = (const float4*)(g_h1s + (long)i * 16);
    float t[16];
#pragma unroll
    for (int q = 0; q < 4; q++) {
        float4 a = av[q], h = hv[q];
        t[4 * q + 0] = fmaxf(fmaf(di, a.x + h.x, b1s[4 * q + 0]), 0.0f);
        t[4 * q + 1] = fmaxf(fmaf(di, a.y + h.y, b1s[4 * q + 1]), 0.0f);
        t[4 * q + 2] = fmaxf(fmaf(di, a.z + h.z, b1s[4 * q + 2]), 0.0f);
        t[4 * q + 3] = fmaxf(fmaf(di, a.w + h.w, b1s[4 * q + 3]), 0.0f);
    }
    float o[7];
#pragma unroll
    for (int c = 0; c < 7; c++) o[c] = 0.0f;
#pragma unroll
    for (int j = 0; j < 16; j++) {
        float tj = t[j];
#pragma unroll
        for (int c = 0; c < 7; c++) o[c] = fmaf(tj, w2s[j * 7 + c], o[c]);
    }
    float4* ov = (float4*)(g_h2s + (long)i * 8);
    ov[0] = make_float4(o[0] * di, o[1] * di, o[2] * di, o[3] * di);
    ov[1] = make_float4(o[4] * di, o[5] * di, o[6] * di, 0.0f);
}

// ---------------- layer-2 scatter: acc2[dst] += h2s[src] ------------------
__global__ __launch_bounds__(256) void scatter2_kernel(const void* __restrict__ ei) {
    int e = blockIdx.x * 256 + threadIdx.x;
    if (e >= NE) return;
    int s, d;
    if (g_is64) {
        const long long* p = (const long long*)ei;
        s = (int)__ldg(p + e); d = (int)__ldg(p + NE + e);
    } else {
        const int* p = (const int*)ei;
        s = __ldg(p + e); d = __ldg(p + NE + e);
    }
    const float4* hv = (const float4*)(g_h2s + (long)s * 8);
    float4 v0 = __ldg(hv + 0), v1 = __ldg(hv + 1);
    float* b = g_acc2 + (long)d * 8;
    red4(b, v0); red4(b + 4, v1);
}

// ---------------- post2: bias + log_softmax -> out -------------------------
__global__ __launch_bounds__(256) void post2_kernel(const float* __restrict__ b2,
                                                    float* __restrict__ out) {
    int i = blockIdx.x * 256 + threadIdx.x;
    if (i >= NN) return;
    float di = g_dinv[i];
    const float4* av = (const float4*)(g_acc2 + (long)i * 8);
    const float4* hv = (const float4*)(g_h2s + (long)i * 8);
    float4 a0 = av[0], a1 = av[1], h0 = hv[0], h1 = hv[1];
    float o[7];
    o[0] = fmaf(di, a0.x + h0.x, __ldg(b2 + 0));
    o[1] = fmaf(di, a0.y + h0.y, __ldg(b2 + 1));
    o[2] = fmaf(di, a0.z + h0.z, __ldg(b2 + 2));
    o[3] = fmaf(di, a0.w + h0.w, __ldg(b2 + 3));
    o[4] = fmaf(di, a1.x + h1.x, __ldg(b2 + 4));
    o[5] = fmaf(di, a1.y + h1.y, __ldg(b2 + 5));
    o[6] = fmaf(di, a1.z + h1.z, __ldg(b2 + 6));
    float m = o[0];
#pragma unroll
    for (int c = 1; c < 7; c++) m = fmaxf(m, o[c]);
    float s = 0.0f;
#pragma unroll
    for (int c = 0; c < 7; c++) s += expf(o[c] - m);
    float l = logf(s);
#pragma unroll
    for (int c = 0; c < 7; c++) out[(long)i * 7 + c] = o[c] - m - l;
}

// ---------------- host ------------------------------------------------------
extern "C" void kernel_launch(void* const* d_in, const int* in_sizes, int n_in,
                              void* d_out, int out_size) {
    const float* x  = (const float*)d_in[0];
    const void*  ei = d_in[1];
    const float* W1 = (const float*)d_in[2];
    const float* b1 = (const float*)d_in[3];
    const float* W2 = (const float*)d_in[4];
    const float* b2 = (const float*)d_in[5];
    float* out = (float*)d_out;

    void *pd, *pa1, *pa2;
    cudaGetSymbolAddress(&pd,  g_deg);
    cudaGetSymbolAddress(&pa1, g_acc1);
    cudaGetSymbolAddress(&pa2, g_acc2);
    cudaMemsetAsync(pd,  0, sizeof(float) * NN);
    cudaMemsetAsync(pa1, 0, sizeof(float) * NN * 16);
    cudaMemsetAsync(pa2, 0, sizeof(float) * NN * 8);

    detect_kernel<<<1, 256>>>((const unsigned*)ei);
    deg_kernel<<<NE / 256, 256>>>(ei);
    dinv_kernel<<<(NN + 255) / 256, 256>>>();

    int smem = (32 * XS_STRIDE + 512 * 16) * sizeof(float);  // 99328 B
    cudaFuncSetAttribute(gemm1_kernel, cudaFuncAttributeMaxDynamicSharedMemorySize, smem);
    gemm1_kernel<<<NN / 32, 256, smem>>>(x, W1);

    scatter1_kernel<<<NE / 256, 256>>>(ei);
    post1_kernel<<<(NN + 255) / 256, 256>>>(b1, W2);
    scatter2_kernel<<<NE / 256, 256>>>(ei);
    post2_kernel<<<(NN + 255) / 256, 256>>>(b2, out);
}

// round 3
// speedup vs baseline: 1.2209x; 1.2209x over previous
#include <cuda_runtime.h>
#include <stdint.h>
#include <math.h>

#define NN 100000
#define NE 3200000

// ---------------- scratch (device globals: no allocation allowed) ----------
__device__ float g_deg[NN];
__device__ float g_dinv[NN];
__device__ float g_h1s[NN * 16];   // (x@W1) * dinv[row]
__device__ float g_acc1[NN * 16];  // scatter accumulator, layer 1
__device__ float g_h2s[NN * 8];    // (relu-out @ W2) * dinv[row], padded to 8
__device__ float g_acc2[NN * 8];   // scatter accumulator, layer 2 (padded)
__device__ int   g_is64;           // edge_index dtype flag

// vector reduction (sm_90+): 4-float global atomic add, no return
__device__ __forceinline__ void red4(float* p, float4 v) {
    asm volatile("red.global.add.v4.f32 [%0], {%1,%2,%3,%4};"
                 :: "l"(p), "f"(v.x), "f"(v.y), "f"(v.z), "f"(v.w) : "memory");
}

__device__ __forceinline__ void cp_async16(unsigned dst_smem, const void* src) {
    asm volatile("cp.async.cg.shared.global [%0], [%1], 16;"
                 :: "r"(dst_smem), "l"(src) : "memory");
}
__device__ __forceinline__ void cp_commit() {
    asm volatile("cp.async.commit_group;" ::: "memory");
}
template <int N>
__device__ __forceinline__ void cp_wait() {
    asm volatile("cp.async.wait_group %0;" :: "n"(N) : "memory");
}

// ---------------- dtype detection -----------------------------------------
// int64 little-endian: every odd 32-bit word (high half) is 0 (ids < 2^31).
// int32: odd words are random node ids in [0,100000) — all-zero is impossible.
__global__ void detect_kernel(const unsigned* __restrict__ ei) {
    __shared__ int nz;
    int tid = threadIdx.x;
    if (tid == 0) nz = 0;
    __syncthreads();
    unsigned v = 0;
#pragma unroll
    for (int i = 0; i < 16; i++) v |= ei[2 * (tid * 16 + i) + 1];
    if (v) nz = 1;
    __syncthreads();
    if (tid == 0) g_is64 = (nz == 0) ? 1 : 0;
}

// ---------------- degree + normalization ----------------------------------
__global__ __launch_bounds__(256) void deg_kernel(const void* __restrict__ ei) {
    int e = blockIdx.x * 256 + threadIdx.x;
    if (e >= NE) return;
    int d;
    if (g_is64) d = (int)__ldg(((const long long*)ei) + NE + e);
    else        d = __ldg(((const int*)ei) + NE + e);
    atomicAdd(&g_deg[d], 1.0f);
}

__global__ __launch_bounds__(256) void dinv_kernel() {
    int i = blockIdx.x * 256 + threadIdx.x;
    if (i < NN) g_dinv[i] = rsqrtf(g_deg[i] + 1.0f);  // +1 = self loop
}

// ---------------- GEMM1: h1s = (x @ W1) * dinv ----------------------------
// One row per thread; all 16 outputs in 8 packed f32x2 accumulators.
// W[k][0..15] read as warp-uniform (broadcast) LDS.128 — conflict-free N=1.
// x staged in K-chunks of 64 via cp.async double-buffering.
#define G1_ROWS 128          // rows per block = threads per block
#define G1_KC   64           // k-chunk
#define G1_NCH  (512 / G1_KC)
#define G1_XST  (G1_KC + 4)  // padded stride (68): lanes land on distinct banks

__global__ __launch_bounds__(G1_ROWS) void gemm1_kernel(const float* __restrict__ x,
                                                        const float* __restrict__ W1) {
    extern __shared__ float smem[];
    float* ws = smem;                          // 512*16 = 8192 floats (32KB)
    float* xs = smem + 512 * 16;               // 2 * 128 * 68 floats (68KB)
    int tid  = threadIdx.x;
    int row0 = blockIdx.x * G1_ROWS;
    int row  = row0 + tid;

    // load W1 (2048 float4, 16 per thread), coalesced
    {
        const float4* Wv = (const float4*)W1;
        float4* wsv = (float4*)ws;
#pragma unroll
        for (int i = 0; i < 16; i++) wsv[tid + G1_ROWS * i] = Wv[tid + G1_ROWS * i];
    }

    unsigned xs_base = (unsigned)__cvta_generic_to_shared(xs);

    // chunk copy: 128 rows x 16 float4, thread does 16; r = idx>>4, q = idx&15
    auto issue_copy = [&](int c, int buf) {
        const float4* xv = (const float4*)x;
        unsigned dst0 = xs_base + buf * (G1_ROWS * G1_XST * 4);
#pragma unroll
        for (int i = 0; i < 16; i++) {
            int idx = tid + G1_ROWS * i;
            int r = idx >> 4, q = idx & 15;
            int gr = row0 + r; if (gr >= NN) gr = NN - 1;
            cp_async16(dst0 + (r * G1_XST + 4 * q) * 4,
                       xv + (long)gr * 128 + c * (G1_KC / 4) + q);
        }
        cp_commit();
    };

    issue_copy(0, 0);

    unsigned long long acc[8];
#pragma unroll
    for (int p = 0; p < 8; p++) acc[p] = 0ULL;

    for (int c = 0; c < G1_NCH; c++) {
        if (c + 1 < G1_NCH) { issue_copy(c + 1, (c + 1) & 1); cp_wait<1>(); }
        else                { cp_wait<0>(); }
        __syncthreads();

        const float* xrow = xs + (c & 1) * (G1_ROWS * G1_XST) + tid * G1_XST;
        const float* wk   = ws + c * G1_KC * 16;
#pragma unroll
        for (int k = 0; k < G1_KC; k += 4) {
            float4 xv = *(const float4*)(xrow + k);
            float xk[4] = {xv.x, xv.y, xv.z, xv.w};
#pragma unroll
            for (int kk = 0; kk < 4; kk++) {
                unsigned long long xb;
                asm("mov.b64 %0,{%1,%1};" : "=l"(xb) : "f"(xk[kk]));
                const ulonglong2* wv = (const ulonglong2*)(wk + (k + kk) * 16);
#pragma unroll
                for (int q = 0; q < 4; q++) {
                    ulonglong2 w2 = wv[q];
                    asm("fma.rn.f32x2 %0, %1, %2, %0;" : "+l"(acc[2*q])   : "l"(xb), "l"(w2.x));
                    asm("fma.rn.f32x2 %0, %1, %2, %0;" : "+l"(acc[2*q+1]) : "l"(xb), "l"(w2.y));
                }
            }
        }
        __syncthreads();  // protect buf (c&1) before it is refilled at c+2
    }

    if (row < NN) {
        float di = g_dinv[row];
        float o[16];
#pragma unroll
        for (int p = 0; p < 8; p++) {
            float a0, a1;
            asm("mov.b64 {%0,%1}, %2;" : "=f"(a0), "=f"(a1) : "l"(acc[p]));
            o[2*p] = a0 * di; o[2*p+1] = a1 * di;
        }
        float4* ov = (float4*)(g_h1s + (long)row * 16);
#pragma unroll
        for (int q = 0; q < 4; q++)
            ov[q] = make_float4(o[4*q], o[4*q+1], o[4*q+2], o[4*q+3]);
    }
}

// ---------------- layer-1 scatter: acc1[dst] += h1s[src] ------------------
__global__ __launch_bounds__(256) void scatter1_kernel(const void* __restrict__ ei) {
    int e = blockIdx.x * 256 + threadIdx.x;
    if (e >= NE) return;
    int s, d;
    if (g_is64) {
        const long long* p = (const long long*)ei;
        s = (int)__ldg(p + e); d = (int)__ldg(p + NE + e);
    } else {
        const int* p = (const int*)ei;
        s = __ldg(p + e); d = __ldg(p + NE + e);
    }
    const float4* hv = (const float4*)(g_h1s + (long)s * 16);
    float4 v0 = __ldg(hv + 0), v1 = __ldg(hv + 1), v2 = __ldg(hv + 2), v3 = __ldg(hv + 3);
    float* b = g_acc1 + (long)d * 16;
    red4(b, v0); red4(b + 4, v1); red4(b + 8, v2); red4(b + 12, v3);
}

// ---------------- post1: relu(dinv*(acc1+h1s)+b1) @ W2, *dinv -> h2s -------
__global__ __launch_bounds__(256) void post1_kernel(const float* __restrict__ b1,
                                                    const float* __restrict__ W2) {
    __shared__ float w2s[112];
    __shared__ float b1s[16];
    int tid = threadIdx.x;
    if (tid < 112) w2s[tid] = W2[tid];
    if (tid < 16)  b1s[tid] = b1[tid];
    __syncthreads();
    int i = blockIdx.x * 256 + tid;
    if (i >= NN) return;
    float di = g_dinv[i];
    const float4* av = (const float4*)(g_acc1 + (long)i * 16);
    const float4* hv = (const float4*)(g_h1s + (long)i * 16);
    float t[16];
#pragma unroll
    for (int q = 0; q < 4; q++) {
        float4 a = av[q], h = hv[q];
        t[4 * q + 0] = fmaxf(fmaf(di, a.x + h.x, b1s[4 * q + 0]), 0.0f);
        t[4 * q + 1] = fmaxf(fmaf(di, a.y + h.y, b1s[4 * q + 1]), 0.0f);
        t[4 * q + 2] = fmaxf(fmaf(di, a.z + h.z, b1s[4 * q + 2]), 0.0f);
        t[4 * q + 3] = fmaxf(fmaf(di, a.w + h.w, b1s[4 * q + 3]), 0.0f);
    }
    float o[7];
#pragma unroll
    for (int c = 0; c < 7; c++) o[c] = 0.0f;
#pragma unroll
    for (int j = 0; j < 16; j++) {
        float tj = t[j];
#pragma unroll
        for (int c = 0; c < 7; c++) o[c] = fmaf(tj, w2s[j * 7 + c], o[c]);
    }
    float4* ov = (float4*)(g_h2s + (long)i * 8);
    ov[0] = make_float4(o[0] * di, o[1] * di, o[2] * di, o[3] * di);
    ov[1] = make_float4(o[4] * di, o[5] * di, o[6] * di, 0.0f);
}

// ---------------- layer-2 scatter: acc2[dst] += h2s[src] ------------------
__global__ __launch_bounds__(256) void scatter2_kernel(const void* __restrict__ ei) {
    int e = blockIdx.x * 256 + threadIdx.x;
    if (e >= NE) return;
    int s, d;
    if (g_is64) {
        const long long* p = (const long long*)ei;
        s = (int)__ldg(p + e); d = (int)__ldg(p + NE + e);
    } else {
        const int* p = (const int*)ei;
        s = __ldg(p + e); d = __ldg(p + NE + e);
    }
    const float4* hv = (const float4*)(g_h2s + (long)s * 8);
    float4 v0 = __ldg(hv + 0), v1 = __ldg(hv + 1);
    float* b = g_acc2 + (long)d * 8;
    red4(b, v0); red4(b + 4, v1);
}

// ---------------- post2: bias + log_softmax -> out -------------------------
__global__ __launch_bounds__(256) void post2_kernel(const float* __restrict__ b2,
                                                    float* __restrict__ out) {
    int i = blockIdx.x * 256 + threadIdx.x;
    if (i >= NN) return;
    float di = g_dinv[i];
    const float4* av = (const float4*)(g_acc2 + (long)i * 8);
    const float4* hv = (const float4*)(g_h2s + (long)i * 8);
    float4 a0 = av[0], a1 = av[1], h0 = hv[0], h1 = hv[1];
    float o[7];
    o[0] = fmaf(di, a0.x + h0.x, __ldg(b2 + 0));
    o[1] = fmaf(di, a0.y + h0.y, __ldg(b2 + 1));
    o[2] = fmaf(di, a0.z + h0.z, __ldg(b2 + 2));
    o[3] = fmaf(di, a0.w + h0.w, __ldg(b2 + 3));
    o[4] = fmaf(di, a1.x + h1.x, __ldg(b2 + 4));
    o[5] = fmaf(di, a1.y + h1.y, __ldg(b2 + 5));
    o[6] = fmaf(di, a1.z + h1.z, __ldg(b2 + 6));
    float m = o[0];
#pragma unroll
    for (int c = 1; c < 7; c++) m = fmaxf(m, o[c]);
    float s = 0.0f;
#pragma unroll
    for (int c = 0; c < 7; c++) s += expf(o[c] - m);
    float l = logf(s);
#pragma unroll
    for (int c = 0; c < 7; c++) out[(long)i * 7 + c] = o[c] - m - l;
}

// ---------------- host ------------------------------------------------------
extern "C" void kernel_launch(void* const* d_in, const int* in_sizes, int n_in,
                              void* d_out, int out_size) {
    const float* x  = (const float*)d_in[0];
    const void*  ei = d_in[1];
    const float* W1 = (const float*)d_in[2];
    const float* b1 = (const float*)d_in[3];
    const float* W2 = (const float*)d_in[4];
    const float* b2 = (const float*)d_in[5];
    float* out = (float*)d_out;

    void *pd, *pa1, *pa2;
    cudaGetSymbolAddress(&pd,  g_deg);
    cudaGetSymbolAddress(&pa1, g_acc1);
    cudaGetSymbolAddress(&pa2, g_acc2);
    cudaMemsetAsync(pd,  0, sizeof(float) * NN);
    cudaMemsetAsync(pa1, 0, sizeof(float) * NN * 16);
    cudaMemsetAsync(pa2, 0, sizeof(float) * NN * 8);

    detect_kernel<<<1, 256>>>((const unsigned*)ei);
    deg_kernel<<<NE / 256, 256>>>(ei);
    dinv_kernel<<<(NN + 255) / 256, 256>>>();

    int smem = (512 * 16 + 2 * G1_ROWS * G1_XST) * sizeof(float);  // 102400 B
    static int smem_set = 0;
    cudaFuncSetAttribute(gemm1_kernel, cudaFuncAttributeMaxDynamicSharedMemorySize, smem);
    (void)smem_set;
    int g1_grid = (NN + G1_ROWS - 1) / G1_ROWS;  // 782
    gemm1_kernel<<<g1_grid, G1_ROWS, smem>>>(x, W1);

    scatter1_kernel<<<NE / 256, 256>>>(ei);
    post1_kernel<<<(NN + 255) / 256, 256>>>(b1, W2);
    scatter2_kernel<<<NE / 256, 256>>>(ei);
    post2_kernel<<<(NN + 255) / 256, 256>>>(b2, out);
}

// round 6
// speedup vs baseline: 1.3535x; 1.1086x over previous
#include <cuda_runtime.h>
#include <stdint.h>
#include <math.h>

#define NN 100000
#define NE 3200000

// ---------------- scratch (device globals: no allocation allowed) ----------
__device__ float g_deg[NN];
__device__ float g_dinv[NN];
__device__ float g_h1s[NN * 16];   // (x@W1) * dinv[row]
__device__ float g_acc1[NN * 16];  // scatter accumulator, layer 1
__device__ float g_h2s[NN * 8];    // (relu-out @ W2) * dinv[row], padded to 8
__device__ float g_acc2[NN * 8];   // scatter accumulator, layer 2 (padded)
__device__ int   g_is64;           // edge_index dtype flag

// vector reduction (sm_90+): 4-float global atomic add, no return
__device__ __forceinline__ void red4(float* p, float4 v) {
    asm volatile("red.global.add.v4.f32 [%0], {%1,%2,%3,%4};"
                 :: "l"(p), "f"(v.x), "f"(v.y), "f"(v.z), "f"(v.w) : "memory");
}

__device__ __forceinline__ void cp_async16(unsigned dst_smem, const void* src) {
    asm volatile("cp.async.cg.shared.global [%0], [%1], 16;"
                 :: "r"(dst_smem), "l"(src) : "memory");
}
__device__ __forceinline__ void cp_commit() {
    asm volatile("cp.async.commit_group;" ::: "memory");
}
template <int N>
__device__ __forceinline__ void cp_wait() {
    asm volatile("cp.async.wait_group %0;" :: "n"(N) : "memory");
}

// ---------------- dtype detection -----------------------------------------
__global__ void detect_kernel(const unsigned* __restrict__ ei) {
    __shared__ int nz;
    int tid = threadIdx.x;
    if (tid == 0) nz = 0;
    __syncthreads();
    unsigned v = 0;
#pragma unroll
    for (int i = 0; i < 16; i++) v |= ei[2 * (tid * 16 + i) + 1];
    if (v) nz = 1;
    __syncthreads();
    if (tid == 0) g_is64 = (nz == 0) ? 1 : 0;
}

// ---------------- degree + normalization ----------------------------------
__global__ __launch_bounds__(256) void deg_kernel(const void* __restrict__ ei) {
    int e = blockIdx.x * 256 + threadIdx.x;
    if (e >= NE) return;
    int d;
    if (g_is64) d = (int)__ldg(((const long long*)ei) + NE + e);
    else        d = __ldg(((const int*)ei) + NE + e);
    atomicAdd(&g_deg[d], 1.0f);
}

__global__ __launch_bounds__(256) void dinv_kernel() {
    int i = blockIdx.x * 256 + threadIdx.x;
    if (i < NN) g_dinv[i] = rsqrtf(g_deg[i] + 1.0f);  // +1 = self loop
}

// ---------------- GEMM1: h1s = (x @ W1) * dinv ----------------------------
// 2 rows per thread, 16 packed-f32x2 accumulators; W[k][0..15] broadcast LDS
// amortized over 16 FFMA2. x staged in K-chunks of 32, cp.async double-buffer.
// 128 threads/CTA -> 256 rows/CTA; smem ~104KB -> 2 CTAs/SM.
#define G1_THR  128
#define G1_ROWS 256          // rows per block
#define G1_KC   32           // k-chunk
#define G1_NCH  (512 / G1_KC)
#define G1_XST  (G1_KC + 4)  // padded stride (36 floats)
#define G1_XBUF (G1_ROWS * G1_XST)

__global__ __launch_bounds__(G1_THR) void gemm1_kernel(const float* __restrict__ x,
                                                       const float* __restrict__ W1) {
    extern __shared__ float smem[];
    float* ws = smem;                          // 512*16 = 8192 floats (32KB)
    float* xs = smem + 512 * 16;               // 2 * 256 * 36 floats (72KB)
    int tid  = threadIdx.x;
    int row0 = blockIdx.x * G1_ROWS;
    int rA   = row0 + tid;
    int rB   = row0 + G1_THR + tid;

    // load W1 (2048 float4, 16 per thread), coalesced
    {
        const float4* Wv = (const float4*)W1;
        float4* wsv = (float4*)ws;
#pragma unroll
        for (int i = 0; i < 16; i++) wsv[tid + G1_THR * i] = Wv[tid + G1_THR * i];
    }

    unsigned xs_base = (unsigned)__cvta_generic_to_shared(xs);

    // chunk copy: 256 rows x 8 float4 = 2048 float4; thread does 16.
    // r = idx >> 3, q = idx & 7
    auto issue_copy = [&](int c, int buf) {
        const float4* xv = (const float4*)x;
        unsigned dst0 = xs_base + buf * (G1_XBUF * 4);
#pragma unroll
        for (int i = 0; i < 16; i++) {
            int idx = tid + G1_THR * i;
            int r = idx >> 3, q = idx & 7;
            int gr = row0 + r; if (gr >= NN) gr = NN - 1;
            cp_async16(dst0 + (r * G1_XST + 4 * q) * 4,
                       xv + (long)gr * 128 + c * (G1_KC / 4) + q);
        }
        cp_commit();
    };

    issue_copy(0, 0);

    unsigned long long accA[8], accB[8];
#pragma unroll
    for (int p = 0; p < 8; p++) { accA[p] = 0ULL; accB[p] = 0ULL; }

    for (int c = 0; c < G1_NCH; c++) {
        if (c + 1 < G1_NCH) { issue_copy(c + 1, (c + 1) & 1); cp_wait<1>(); }
        else                { cp_wait<0>(); }
        __syncthreads();

        const float* xrA = xs + (c & 1) * G1_XBUF + tid * G1_XST;
        const float* xrB = xrA + G1_THR * G1_XST;
        const float* wk  = ws + c * G1_KC * 16;
#pragma unroll
        for (int k = 0; k < G1_KC; k += 4) {
            float4 a4 = *(const float4*)(xrA + k);
            float4 b4 = *(const float4*)(xrB + k);
            float ak[4] = {a4.x, a4.y, a4.z, a4.w};
            float bk[4] = {b4.x, b4.y, b4.z, b4.w};
#pragma unroll
            for (int kk = 0; kk < 4; kk++) {
                unsigned long long xa, xb;
                asm("mov.b64 %0,{%1,%1};" : "=l"(xa) : "f"(ak[kk]));
                asm("mov.b64 %0,{%1,%1};" : "=l"(xb) : "f"(bk[kk]));
                const ulonglong2* wv = (const ulonglong2*)(wk + (k + kk) * 16);
#pragma unroll
                for (int q = 0; q < 4; q++) {
                    ulonglong2 w2 = wv[q];
                    asm("fma.rn.f32x2 %0, %1, %2, %0;" : "+l"(accA[2*q])   : "l"(xa), "l"(w2.x));
                    asm("fma.rn.f32x2 %0, %1, %2, %0;" : "+l"(accA[2*q+1]) : "l"(xa), "l"(w2.y));
                    asm("fma.rn.f32x2 %0, %1, %2, %0;" : "+l"(accB[2*q])   : "l"(xb), "l"(w2.x));
                    asm("fma.rn.f32x2 %0, %1, %2, %0;" : "+l"(accB[2*q+1]) : "l"(xb), "l"(w2.y));
                }
            }
        }
        __syncthreads();  // protect buf (c&1) before refill at c+2
    }

    if (rA < NN) {
        float di = g_dinv[rA];
        float o[16];
#pragma unroll
        for (int p = 0; p < 8; p++) {
            float a0, a1;
            asm("mov.b64 {%0,%1}, %2;" : "=f"(a0), "=f"(a1) : "l"(accA[p]));
            o[2*p] = a0 * di; o[2*p+1] = a1 * di;
        }
        float4* ov = (float4*)(g_h1s + (long)rA * 16);
#pragma unroll
        for (int q = 0; q < 4; q++)
            ov[q] = make_float4(o[4*q], o[4*q+1], o[4*q+2], o[4*q+3]);
    }
    if (rB < NN) {
        float di = g_dinv[rB];
        float o[16];
#pragma unroll
        for (int p = 0; p < 8; p++) {
            float a0, a1;
            asm("mov.b64 {%0,%1}, %2;" : "=f"(a0), "=f"(a1) : "l"(accB[p]));
            o[2*p] = a0 * di; o[2*p+1] = a1 * di;
        }
        float4* ov = (float4*)(g_h1s + (long)rB * 16);
#pragma unroll
        for (int q = 0; q < 4; q++)
            ov[q] = make_float4(o[4*q], o[4*q+1], o[4*q+2], o[4*q+3]);
    }
}

// ---------------- layer-1 scatter: acc1[dst] += h1s[src] ------------------
__global__ __launch_bounds__(256) void scatter1_kernel(const void* __restrict__ ei) {
    int e = blockIdx.x * 256 + threadIdx.x;
    if (e >= NE) return;
    int s, d;
    if (g_is64) {
        const long long* p = (const long long*)ei;
        s = (int)__ldg(p + e); d = (int)__ldg(p + NE + e);
    } else {
        const int* p = (const int*)ei;
        s = __ldg(p + e); d = __ldg(p + NE + e);
    }
    const float4* hv = (const float4*)(g_h1s + (long)s * 16);
    float4 v0 = __ldg(hv + 0), v1 = __ldg(hv + 1), v2 = __ldg(hv + 2), v3 = __ldg(hv + 3);
    float* b = g_acc1 + (long)d * 16;
    red4(b, v0); red4(b + 4, v1); red4(b + 8, v2); red4(b + 12, v3);
}

// ---------------- post1: relu(dinv*(acc1+h1s)+b1) @ W2, *dinv -> h2s -------
__global__ __launch_bounds__(256) void post1_kernel(const float* __restrict__ b1,
                                                    const float* __restrict__ W2) {
    __shared__ float w2s[112];
    __shared__ float b1s[16];
    int tid = threadIdx.x;
    if (tid < 112) w2s[tid] = W2[tid];
    if (tid < 16)  b1s[tid] = b1[tid];
    __syncthreads();
    int i = blockIdx.x * 256 + tid;
    if (i >= NN) return;
    float di = g_dinv[i];
    const float4* av = (const float4*)(g_acc1 + (long)i * 16);
    const float4* hv = (const float4*)(g_h1s + (long)i * 16);
    float t[16];
#pragma unroll
    for (int q = 0; q < 4; q++) {
        float4 a = av[q], h = hv[q];
        t[4 * q + 0] = fmaxf(fmaf(di, a.x + h.x, b1s[4 * q + 0]), 0.0f);
        t[4 * q + 1] = fmaxf(fmaf(di, a.y + h.y, b1s[4 * q + 1]), 0.0f);
        t[4 * q + 2] = fmaxf(fmaf(di, a.z + h.z, b1s[4 * q + 2]), 0.0f);
        t[4 * q + 3] = fmaxf(fmaf(di, a.w + h.w, b1s[4 * q + 3]), 0.0f);
    }
    float o[7];
#pragma unroll
    for (int c = 0; c < 7; c++) o[c] = 0.0f;
#pragma unroll
    for (int j = 0; j < 16; j++) {
        float tj = t[j];
#pragma unroll
        for (int c = 0; c < 7; c++) o[c] = fmaf(tj, w2s[j * 7 + c], o[c]);
    }
    float4* ov = (float4*)(g_h2s + (long)i * 8);
    ov[0] = make_float4(o[0] * di, o[1] * di, o[2] * di, o[3] * di);
    ov[1] = make_float4(o[4] * di, o[5] * di, o[6] * di, 0.0f);
}

// ---------------- layer-2 scatter: acc2[dst] += h2s[src] ------------------
__global__ __launch_bounds__(256) void scatter2_kernel(const void* __restrict__ ei) {
    int e = blockIdx.x * 256 + threadIdx.x;
    if (e >= NE) return;
    int s, d;
    if (g_is64) {
        const long long* p = (const long long*)ei;
        s = (int)__ldg(p + e); d = (int)__ldg(p + NE + e);
    } else {
        const int* p = (const int*)ei;
        s = __ldg(p + e); d = __ldg(p + NE + e);
    }
    const float4* hv = (const float4*)(g_h2s + (long)s * 8);
    float4 v0 = __ldg(hv + 0), v1 = __ldg(hv + 1);
    float* b = g_acc2 + (long)d * 8;
    red4(b, v0); red4(b + 4, v1);
}

// ---------------- post2: bias + log_softmax -> out -------------------------
__global__ __launch_bounds__(256) void post2_kernel(const float* __restrict__ b2,
                                                    float* __restrict__ out) {
    int i = blockIdx.x * 256 + threadIdx.x;
    if (i >= NN) return;
    float di = g_dinv[i];
    const float4* av = (const float4*)(g_acc2 + (long)i * 8);
    const float4* hv = (const float4*)(g_h2s + (long)i * 8);
    float4 a0 = av[0], a1 = av[1], h0 = hv[0], h1 = hv[1];
    float o[7];
    o[0] = fmaf(di, a0.x + h0.x, __ldg(b2 + 0));
    o[1] = fmaf(di, a0.y + h0.y, __ldg(b2 + 1));
    o[2] = fmaf(di, a0.z + h0.z, __ldg(b2 + 2));
    o[3] = fmaf(di, a0.w + h0.w, __ldg(b2 + 3));
    o[4] = fmaf(di, a1.x + h1.x, __ldg(b2 + 4));
    o[5] = fmaf(di, a1.y + h1.y, __ldg(b2 + 5));
    o[6] = fmaf(di, a1.z + h1.z, __ldg(b2 + 6));
    float m = o[0];
#pragma unroll
    for (int c = 1; c < 7; c++) m = fmaxf(m, o[c]);
    float s = 0.0f;
#pragma unroll
    for (int c = 0; c < 7; c++) s += expf(o[c] - m);
    float l = logf(s);
#pragma unroll
    for (int c = 0; c < 7; c++) out[(long)i * 7 + c] = o[c] - m - l;
}

// ---------------- host ------------------------------------------------------
extern "C" void kernel_launch(void* const* d_in, const int* in_sizes, int n_in,
                              void* d_out, int out_size) {
    const float* x  = (const float*)d_in[0];
    const void*  ei = d_in[1];
    const float* W1 = (const float*)d_in[2];
    const float* b1 = (const float*)d_in[3];
    const float* W2 = (const float*)d_in[4];
    const float* b2 = (const float*)d_in[5];
    float* out = (float*)d_out;

    void *pd, *pa1, *pa2;
    cudaGetSymbolAddress(&pd,  g_deg);
    cudaGetSymbolAddress(&pa1, g_acc1);
    cudaGetSymbolAddress(&pa2, g_acc2);
    cudaMemsetAsync(pd,  0, sizeof(float) * NN);
    cudaMemsetAsync(pa1, 0, sizeof(float) * NN * 16);
    cudaMemsetAsync(pa2, 0, sizeof(float) * NN * 8);

    detect_kernel<<<1, 256>>>((const unsigned*)ei);
    deg_kernel<<<NE / 256, 256>>>(ei);
    dinv_kernel<<<(NN + 255) / 256, 256>>>();

    int smem = (512 * 16 + 2 * G1_XBUF) * sizeof(float);  // 32768 + 73728 = 106496 B
    cudaFuncSetAttribute(gemm1_kernel, cudaFuncAttributeMaxDynamicSharedMemorySize, smem);
    int g1_grid = (NN + G1_ROWS - 1) / G1_ROWS;  // 391
    gemm1_kernel<<<g1_grid, G1_THR, smem>>>(x, W1);

    scatter1_kernel<<<NE / 256, 256>>>(ei);
    post1_kernel<<<(NN + 255) / 256, 256>>>(b1, W2);
    scatter2_kernel<<<NE / 256, 256>>>(ei);
    post2_kernel<<<(NN + 255) / 256, 256>>>(b2, out);
}

// round 8
// speedup vs baseline: 1.3811x; 1.0204x over previous
#include <cuda_runtime.h>
#include <stdint.h>
#include <math.h>

#define NN 100000
#define NE 3200000
#define NBLK 391          // ceil(NN/256)

// ---------------- scratch (device globals: no allocation allowed) ----------
__device__ int   g_cnt[NN];        // in-degree histogram (excl self-loop)
__device__ int   g_off[NN + 1];    // CSR offsets
__device__ int   g_cur[NN];        // fill cursors
__device__ int   g_bsum[NBLK + 1];
__device__ int   g_bbase[NBLK + 1];
__device__ int   g_csr_src[NE];    // CSR: src ids grouped by dst
__device__ float g_dinv[NN];
__device__ float g_h1s[NN * 16];   // (x@W1) * dinv[row]
__device__ float g_h2s[NN * 8];    // (relu-out @ W2) * dinv[row], padded to 8
__device__ int   g_is64;           // edge_index dtype flag

__device__ __forceinline__ void cp_async16(unsigned dst_smem, const void* src) {
    asm volatile("cp.async.cg.shared.global [%0], [%1], 16;"
                 :: "r"(dst_smem), "l"(src) : "memory");
}
__device__ __forceinline__ void cp_commit() {
    asm volatile("cp.async.commit_group;" ::: "memory");
}
template <int N>
__device__ __forceinline__ void cp_wait() {
    asm volatile("cp.async.wait_group %0;" :: "n"(N) : "memory");
}

// ---------------- dtype detection -----------------------------------------
__global__ void detect_kernel(const unsigned* __restrict__ ei) {
    __shared__ int nz;
    int tid = threadIdx.x;
    if (tid == 0) nz = 0;
    __syncthreads();
    unsigned v = 0;
#pragma unroll
    for (int i = 0; i < 16; i++) v |= ei[2 * (tid * 16 + i) + 1];
    if (v) nz = 1;
    __syncthreads();
    if (tid == 0) g_is64 = (nz == 0) ? 1 : 0;
}

// ---------------- histogram of dst ----------------------------------------
__global__ __launch_bounds__(256) void hist_kernel(const void* __restrict__ ei) {
    int e = blockIdx.x * 256 + threadIdx.x;
    if (e >= NE) return;
    int d;
    if (g_is64) d = (int)__ldg(((const long long*)ei) + NE + e);
    else        d = __ldg(((const int*)ei) + NE + e);
    atomicAdd(&g_cnt[d], 1);
}

// ---------------- scan: A (block sums) ------------------------------------
__global__ __launch_bounds__(256) void scanA_kernel() {
    __shared__ int s[256];
    int tid = threadIdx.x;
    int t = blockIdx.x * 256 + tid;
    int c = (t < NN) ? g_cnt[t] : 0;
    s[tid] = c;
    __syncthreads();
#pragma unroll
    for (int o = 128; o > 0; o >>= 1) {
        if (tid < o) s[tid] += s[tid + o];
        __syncthreads();
    }
    if (tid == 0) g_bsum[blockIdx.x] = s[0];
}

// ---------------- scan: B (scan 391 block sums) ----------------------------
__global__ __launch_bounds__(512) void scanB_kernel() {
    __shared__ int s[512];
    int tid = threadIdx.x;
    int v = (tid < NBLK) ? g_bsum[tid] : 0;
    s[tid] = v;
    __syncthreads();
#pragma unroll
    for (int st = 1; st < 512; st <<= 1) {
        int a = (tid >= st) ? s[tid - st] : 0;
        __syncthreads();
        s[tid] += a;
        __syncthreads();
    }
    if (tid < NBLK) g_bbase[tid] = s[tid] - v;   // exclusive
    if (tid == 0) g_off[NN] = NE;
}

// ---------------- scan: C (local scan + base; also dinv) -------------------
__global__ __launch_bounds__(256) void scanC_kernel() {
    __shared__ int s[256];
    int tid = threadIdx.x;
    int t = blockIdx.x * 256 + tid;
    int c = (t < NN) ? g_cnt[t] : 0;
    s[tid] = c;
    __syncthreads();
#pragma unroll
    for (int st = 1; st < 256; st <<= 1) {
        int a = (tid >= st) ? s[tid - st] : 0;
        __syncthreads();
        s[tid] += a;
        __syncthreads();
    }
    if (t < NN) {
        int off = g_bbase[blockIdx.x] + s[tid] - c;  // exclusive
        g_off[t] = off;
        g_cur[t] = off;
        g_dinv[t] = rsqrtf((float)c + 1.0f);         // +1 = self loop
    }
}

// ---------------- CSR fill --------------------------------------------------
__global__ __launch_bounds__(256) void fill_kernel(const void* __restrict__ ei) {
    int e = blockIdx.x * 256 + threadIdx.x;
    if (e >= NE) return;
    int sv, d;
    if (g_is64) {
        const long long* p = (const long long*)ei;
        sv = (int)__ldg(p + e); d = (int)__ldg(p + NE + e);
    } else {
        const int* p = (const int*)ei;
        sv = __ldg(p + e); d = __ldg(p + NE + e);
    }
    int pos = atomicAdd(&g_cur[d], 1);
    g_csr_src[pos] = sv;
}

// ---------------- GEMM1: h1s = (x @ W1) * dinv ----------------------------
#define G1_THR  128
#define G1_ROWS 256
#define G1_KC   32
#define G1_NCH  (512 / G1_KC)
#define G1_XST  (G1_KC + 4)
#define G1_XBUF (G1_ROWS * G1_XST)

__global__ __launch_bounds__(G1_THR) void gemm1_kernel(const float* __restrict__ x,
                                                       const float* __restrict__ W1) {
    extern __shared__ float smem[];
    float* ws = smem;
    float* xs = smem + 512 * 16;
    int tid  = threadIdx.x;
    int row0 = blockIdx.x * G1_ROWS;
    int rA   = row0 + tid;
    int rB   = row0 + G1_THR + tid;

    {
        const float4* Wv = (const float4*)W1;
        float4* wsv = (float4*)ws;
#pragma unroll
        for (int i = 0; i < 16; i++) wsv[tid + G1_THR * i] = Wv[tid + G1_THR * i];
    }

    unsigned xs_base = (unsigned)__cvta_generic_to_shared(xs);

    auto issue_copy = [&](int c, int buf) {
        const float4* xv = (const float4*)x;
        unsigned dst0 = xs_base + buf * (G1_XBUF * 4);
#pragma unroll
        for (int i = 0; i < 16; i++) {
            int idx = tid + G1_THR * i;
            int r = idx >> 3, q = idx & 7;
            int gr = row0 + r; if (gr >= NN) gr = NN - 1;
            cp_async16(dst0 + (r * G1_XST + 4 * q) * 4,
                       xv + (long)gr * 128 + c * (G1_KC / 4) + q);
        }
        cp_commit();
    };

    issue_copy(0, 0);

    unsigned long long accA[8], accB[8];
#pragma unroll
    for (int p = 0; p < 8; p++) { accA[p] = 0ULL; accB[p] = 0ULL; }

    for (int c = 0; c < G1_NCH; c++) {
        if (c + 1 < G1_NCH) { issue_copy(c + 1, (c + 1) & 1); cp_wait<1>(); }
        else                { cp_wait<0>(); }
        __syncthreads();

        const float* xrA = xs + (c & 1) * G1_XBUF + tid * G1_XST;
        const float* xrB = xrA + G1_THR * G1_XST;
        const float* wk  = ws + c * G1_KC * 16;
#pragma unroll
        for (int k = 0; k < G1_KC; k += 4) {
            float4 a4 = *(const float4*)(xrA + k);
            float4 b4 = *(const float4*)(xrB + k);
            float ak[4] = {a4.x, a4.y, a4.z, a4.w};
            float bk[4] = {b4.x, b4.y, b4.z, b4.w};
#pragma unroll
            for (int kk = 0; kk < 4; kk++) {
                unsigned long long xa, xb;
                asm("mov.b64 %0,{%1,%1};" : "=l"(xa) : "f"(ak[kk]));
                asm("mov.b64 %0,{%1,%1};" : "=l"(xb) : "f"(bk[kk]));
                const ulonglong2* wv = (const ulonglong2*)(wk + (k + kk) * 16);
#pragma unroll
                for (int q = 0; q < 4; q++) {
                    ulonglong2 w2 = wv[q];
                    asm("fma.rn.f32x2 %0, %1, %2, %0;" : "+l"(accA[2*q])   : "l"(xa), "l"(w2.x));
                    asm("fma.rn.f32x2 %0, %1, %2, %0;" : "+l"(accA[2*q+1]) : "l"(xa), "l"(w2.y));
                    asm("fma.rn.f32x2 %0, %1, %2, %0;" : "+l"(accB[2*q])   : "l"(xb), "l"(w2.x));
                    asm("fma.rn.f32x2 %0, %1, %2, %0;" : "+l"(accB[2*q+1]) : "l"(xb), "l"(w2.y));
                }
            }
        }
        __syncthreads();
    }

    if (rA < NN) {
        float di = g_dinv[rA];
        float o[16];
#pragma unroll
        for (int p = 0; p < 8; p++) {
            float a0, a1;
            asm("mov.b64 {%0,%1}, %2;" : "=f"(a0), "=f"(a1) : "l"(accA[p]));
            o[2*p] = a0 * di; o[2*p+1] = a1 * di;
        }
        float4* ov = (float4*)(g_h1s + (long)rA * 16);
#pragma unroll
        for (int q = 0; q < 4; q++)
            ov[q] = make_float4(o[4*q], o[4*q+1], o[4*q+2], o[4*q+3]);
    }
    if (rB < NN) {
        float di = g_dinv[rB];
        float o[16];
#pragma unroll
        for (int p = 0; p < 8; p++) {
            float a0, a1;
            asm("mov.b64 {%0,%1}, %2;" : "=f"(a0), "=f"(a1) : "l"(accB[p]));
            o[2*p] = a0 * di; o[2*p+1] = a1 * di;
        }
        float4* ov = (float4*)(g_h1s + (long)rB * 16);
#pragma unroll
        for (int q = 0; q < 4; q++)
            ov[q] = make_float4(o[4*q], o[4*q+1], o[4*q+2], o[4*q+3]);
    }
}

// ---------------- gather1 (+fused post1) -----------------------------------
// One thread per node: acc = sum_{s in in(i)} h1s[s]; then
// t = relu(dinv*(acc + h1s[i]) + b1); h2s[i] = (t @ W2) * dinv, padded to 8.
__global__ __launch_bounds__(256) void gather1_kernel(const float* __restrict__ b1,
                                                      const float* __restrict__ W2) {
    __shared__ float w2s[112];
    __shared__ float b1s[16];
    int tid = threadIdx.x;
    if (tid < 112) w2s[tid] = W2[tid];
    if (tid < 16)  b1s[tid] = b1[tid];
    __syncthreads();
    int i = blockIdx.x * 256 + tid;
    if (i >= NN) return;

    int beg = g_off[i], end = g_off[i + 1];
    float acc[16];
#pragma unroll
    for (int q = 0; q < 16; q++) acc[q] = 0.0f;

    int j = beg;
    for (; j + 1 < end; j += 2) {
        int s0 = __ldg(&g_csr_src[j]);
        int s1 = __ldg(&g_csr_src[j + 1]);
        const float4* p0 = (const float4*)(g_h1s + (long)s0 * 16);
        const float4* p1 = (const float4*)(g_h1s + (long)s1 * 16);
        float4 a0 = __ldg(p0 + 0), a1 = __ldg(p0 + 1), a2 = __ldg(p0 + 2), a3 = __ldg(p0 + 3);
        float4 c0 = __ldg(p1 + 0), c1 = __ldg(p1 + 1), c2 = __ldg(p1 + 2), c3 = __ldg(p1 + 3);
        acc[0] += a0.x + c0.x;  acc[1] += a0.y + c0.y;  acc[2] += a0.z + c0.z;  acc[3] += a0.w + c0.w;
        acc[4] += a1.x + c1.x;  acc[5] += a1.y + c1.y;  acc[6] += a1.z + c1.z;  acc[7] += a1.w + c1.w;
        acc[8] += a2.x + c2.x;  acc[9] += a2.y + c2.y;  acc[10] += a2.z + c2.z; acc[11] += a2.w + c2.w;
        acc[12] += a3.x + c3.x; acc[13] += a3.y + c3.y; acc[14] += a3.z + c3.z; acc[15] += a3.w + c3.w;
    }
    if (j < end) {
        int s0 = __ldg(&g_csr_src[j]);
        const float4* p0 = (const float4*)(g_h1s + (long)s0 * 16);
        float4 a0 = __ldg(p0 + 0), a1 = __ldg(p0 + 1), a2 = __ldg(p0 + 2), a3 = __ldg(p0 + 3);
        acc[0] += a0.x;  acc[1] += a0.y;  acc[2] += a0.z;  acc[3] += a0.w;
        acc[4] += a1.x;  acc[5] += a1.y;  acc[6] += a1.z;  acc[7] += a1.w;
        acc[8] += a2.x;  acc[9] += a2.y;  acc[10] += a2.z; acc[11] += a2.w;
        acc[12] += a3.x; acc[13] += a3.y; acc[14] += a3.z; acc[15] += a3.w;
    }

    float di = g_dinv[i];
    const float4* hv = (const float4*)(g_h1s + (long)i * 16);
    float t[16];
#pragma unroll
    for (int q = 0; q < 4; q++) {
        float4 h = hv[q];
        t[4*q+0] = fmaxf(fmaf(di, acc[4*q+0] + h.x, b1s[4*q+0]), 0.0f);
        t[4*q+1] = fmaxf(fmaf(di, acc[4*q+1] + h.y, b1s[4*q+1]), 0.0f);
        t[4*q+2] = fmaxf(fmaf(di, acc[4*q+2] + h.z, b1s[4*q+2]), 0.0f);
        t[4*q+3] = fmaxf(fmaf(di, acc[4*q+3] + h.w, b1s[4*q+3]), 0.0f);
    }
    float o[7];
#pragma unroll
    for (int c = 0; c < 7; c++) o[c] = 0.0f;
#pragma unroll
    for (int jj = 0; jj < 16; jj++) {
        float tj = t[jj];
#pragma unroll
        for (int c = 0; c < 7; c++) o[c] = fmaf(tj, w2s[jj * 7 + c], o[c]);
    }
    float4* ov = (float4*)(g_h2s + (long)i * 8);
    ov[0] = make_float4(o[0] * di, o[1] * di, o[2] * di, o[3] * di);
    ov[1] = make_float4(o[4] * di, o[5] * di, o[6] * di, 0.0f);
}

// ---------------- gather2 (+fused post2: log_softmax) ----------------------
__global__ __launch_bounds__(256) void gather2_kernel(const float* __restrict__ b2,
                                                      float* __restrict__ out) {
    int i = blockIdx.x * 256 + threadIdx.x;
    if (i >= NN) return;

    int beg = g_off[i], end = g_off[i + 1];
    float acc[8];
#pragma unroll
    for (int q = 0; q < 8; q++) acc[q] = 0.0f;

    int j = beg;
    for (; j + 1 < end; j += 2) {
        int s0 = __ldg(&g_csr_src[j]);
        int s1 = __ldg(&g_csr_src[j + 1]);
        const float4* p0 = (const float4*)(g_h2s + (long)s0 * 8);
        const float4* p1 = (const float4*)(g_h2s + (long)s1 * 8);
        float4 a0 = __ldg(p0 + 0), a1 = __ldg(p0 + 1);
        float4 c0 = __ldg(p1 + 0), c1 = __ldg(p1 + 1);
        acc[0] += a0.x + c0.x; acc[1] += a0.y + c0.y; acc[2] += a0.z + c0.z; acc[3] += a0.w + c0.w;
        acc[4] += a1.x + c1.x; acc[5] += a1.y + c1.y; acc[6] += a1.z + c1.z; acc[7] += a1.w + c1.w;
    }
    if (j < end) {
        int s0 = __ldg(&g_csr_src[j]);
        const float4* p0 = (const float4*)(g_h2s + (long)s0 * 8);
        float4 a0 = __ldg(p0 + 0), a1 = __ldg(p0 + 1);
        acc[0] += a0.x; acc[1] += a0.y; acc[2] += a0.z; acc[3] += a0.w;
        acc[4] += a1.x; acc[5] += a1.y; acc[6] += a1.z; acc[7] += a1.w;
    }

    float di = g_dinv[i];
    const float4* hv = (const float4*)(g_h2s + (long)i * 8);
    float4 h0 = hv[0], h1 = hv[1];
    float o[7];
    o[0] = fmaf(di, acc[0] + h0.x, __ldg(b2 + 0));
    o[1] = fmaf(di, acc[1] + h0.y, __ldg(b2 + 1));
    o[2] = fmaf(di, acc[2] + h0.z, __ldg(b2 + 2));
    o[3] = fmaf(di, acc[3] + h0.w, __ldg(b2 + 3));
    o[4] = fmaf(di, acc[4] + h1.x, __ldg(b2 + 4));
    o[5] = fmaf(di, acc[5] + h1.y, __ldg(b2 + 5));
    o[6] = fmaf(di, acc[6] + h1.z, __ldg(b2 + 6));
    float m = o[0];
#pragma unroll
    for (int c = 1; c < 7; c++) m = fmaxf(m, o[c]);
    float s = 0.0f;
#pragma unroll
    for (int c = 0; c < 7; c++) s += expf(o[c] - m);
    float l = logf(s);
#pragma unroll
    for (int c = 0; c < 7; c++) out[(long)i * 7 + c] = o[c] - m - l;
}

// ---------------- host ------------------------------------------------------
extern "C" void kernel_launch(void* const* d_in, const int* in_sizes, int n_in,
                              void* d_out, int out_size) {
    const float* x  = (const float*)d_in[0];
    const void*  ei = d_in[1];
    const float* W1 = (const float*)d_in[2];
    const float* b1 = (const float*)d_in[3];
    const float* W2 = (const float*)d_in[4];
    const float* b2 = (const float*)d_in[5];
    float* out = (float*)d_out;

    void* pc;
    cudaGetSymbolAddress(&pc, g_cnt);
    cudaMemsetAsync(pc, 0, sizeof(int) * NN);

    detect_kernel<<<1, 256>>>((const unsigned*)ei);
    hist_kernel<<<NE / 256, 256>>>(ei);
    scanA_kernel<<<NBLK, 256>>>();
    scanB_kernel<<<1, 512>>>();
    scanC_kernel<<<NBLK, 256>>>();
    fill_kernel<<<NE / 256, 256>>>(ei);

    int smem = (512 * 16 + 2 * G1_XBUF) * sizeof(float);  // 106496 B
    cudaFuncSetAttribute(gemm1_kernel, cudaFuncAttributeMaxDynamicSharedMemorySize, smem);
    gemm1_kernel<<<(NN + G1_ROWS - 1) / G1_ROWS, G1_THR, smem>>>(x, W1);

    gather1_kernel<<<NBLK, 256>>>(b1, W2);
    gather2_kernel<<<NBLK, 256>>>(b2, out);
}

// round 9
// speedup vs baseline: 1.6817x; 1.2176x over previous
#include <cuda_runtime.h>
#include <stdint.h>
#include <math.h>

#define NN 100000
#define NE 3200000
#define NBLK 391          // ceil(NN/256)
#define G_NPB 32          // nodes per block in gather kernels (256 thr / 8)
#define G_NBLK ((NN + G_NPB - 1) / G_NPB)

// ---------------- scratch (device globals: no allocation allowed) ----------
__device__ int   g_cnt[NN];        // in-degree histogram (excl self-loop)
__device__ int   g_off[NN + 1];    // CSR offsets
__device__ int   g_cur[NN];        // fill cursors
__device__ int   g_bsum[NBLK + 1];
__device__ int   g_bbase[NBLK + 1];
__device__ int   g_csr_src[NE];    // CSR: src ids grouped by dst
__device__ float g_dinv[NN];
__device__ float g_h1s[NN * 16];   // (x@W1) * dinv[row]
__device__ float g_h2s[NN * 8];    // (relu-out @ W2) * dinv[row], padded to 8
__device__ int   g_is64;           // edge_index dtype flag

__device__ __forceinline__ void cp_async16(unsigned dst_smem, const void* src) {
    asm volatile("cp.async.cg.shared.global [%0], [%1], 16;"
                 :: "r"(dst_smem), "l"(src) : "memory");
}
__device__ __forceinline__ void cp_commit() {
    asm volatile("cp.async.commit_group;" ::: "memory");
}
template <int N>
__device__ __forceinline__ void cp_wait() {
    asm volatile("cp.async.wait_group %0;" :: "n"(N) : "memory");
}

// ---------------- dtype detection -----------------------------------------
__global__ void detect_kernel(const unsigned* __restrict__ ei) {
    __shared__ int nz;
    int tid = threadIdx.x;
    if (tid == 0) nz = 0;
    __syncthreads();
    unsigned v = 0;
#pragma unroll
    for (int i = 0; i < 16; i++) v |= ei[2 * (tid * 16 + i) + 1];
    if (v) nz = 1;
    __syncthreads();
    if (tid == 0) g_is64 = (nz == 0) ? 1 : 0;
}

// ---------------- histogram of dst ----------------------------------------
__global__ __launch_bounds__(256) void hist_kernel(const void* __restrict__ ei) {
    int e = blockIdx.x * 256 + threadIdx.x;
    if (e >= NE) return;
    int d;
    if (g_is64) d = (int)__ldg(((const long long*)ei) + NE + e);
    else        d = __ldg(((const int*)ei) + NE + e);
    atomicAdd(&g_cnt[d], 1);
}

// ---------------- scan: A (block sums) ------------------------------------
__global__ __launch_bounds__(256) void scanA_kernel() {
    __shared__ int s[256];
    int tid = threadIdx.x;
    int t = blockIdx.x * 256 + tid;
    int c = (t < NN) ? g_cnt[t] : 0;
    s[tid] = c;
    __syncthreads();
#pragma unroll
    for (int o = 128; o > 0; o >>= 1) {
        if (tid < o) s[tid] += s[tid + o];
        __syncthreads();
    }
    if (tid == 0) g_bsum[blockIdx.x] = s[0];
}

// ---------------- scan: B (scan 391 block sums) ----------------------------
__global__ __launch_bounds__(512) void scanB_kernel() {
    __shared__ int s[512];
    int tid = threadIdx.x;
    int v = (tid < NBLK) ? g_bsum[tid] : 0;
    s[tid] = v;
    __syncthreads();
#pragma unroll
    for (int st = 1; st < 512; st <<= 1) {
        int a = (tid >= st) ? s[tid - st] : 0;
        __syncthreads();
        s[tid] += a;
        __syncthreads();
    }
    if (tid < NBLK) g_bbase[tid] = s[tid] - v;   // exclusive
    if (tid == 0) g_off[NN] = NE;
}

// ---------------- scan: C (local scan + base; also dinv) -------------------
__global__ __launch_bounds__(256) void scanC_kernel() {
    __shared__ int s[256];
    int tid = threadIdx.x;
    int t = blockIdx.x * 256 + tid;
    int c = (t < NN) ? g_cnt[t] : 0;
    s[tid] = c;
    __syncthreads();
#pragma unroll
    for (int st = 1; st < 256; st <<= 1) {
        int a = (tid >= st) ? s[tid - st] : 0;
        __syncthreads();
        s[tid] += a;
        __syncthreads();
    }
    if (t < NN) {
        int off = g_bbase[blockIdx.x] + s[tid] - c;  // exclusive
        g_off[t] = off;
        g_cur[t] = off;
        g_dinv[t] = rsqrtf((float)c + 1.0f);         // +1 = self loop
    }
}

// ---------------- CSR fill --------------------------------------------------
__global__ __launch_bounds__(256) void fill_kernel(const void* __restrict__ ei) {
    int e = blockIdx.x * 256 + threadIdx.x;
    if (e >= NE) return;
    int sv, d;
    if (g_is64) {
        const long long* p = (const long long*)ei;
        sv = (int)__ldg(p + e); d = (int)__ldg(p + NE + e);
    } else {
        const int* p = (const int*)ei;
        sv = __ldg(p + e); d = __ldg(p + NE + e);
    }
    int pos = atomicAdd(&g_cur[d], 1);
    g_csr_src[pos] = sv;
}

// ---------------- GEMM1: h1s = (x @ W1) * dinv ----------------------------
#define G1_THR  128
#define G1_ROWS 256
#define G1_KC   32
#define G1_NCH  (512 / G1_KC)
#define G1_XST  (G1_KC + 4)
#define G1_XBUF (G1_ROWS * G1_XST)

__global__ __launch_bounds__(G1_THR) void gemm1_kernel(const float* __restrict__ x,
                                                       const float* __restrict__ W1) {
    extern __shared__ float smem[];
    float* ws = smem;
    float* xs = smem + 512 * 16;
    int tid  = threadIdx.x;
    int row0 = blockIdx.x * G1_ROWS;
    int rA   = row0 + tid;
    int rB   = row0 + G1_THR + tid;

    {
        const float4* Wv = (const float4*)W1;
        float4* wsv = (float4*)ws;
#pragma unroll
        for (int i = 0; i < 16; i++) wsv[tid + G1_THR * i] = Wv[tid + G1_THR * i];
    }

    unsigned xs_base = (unsigned)__cvta_generic_to_shared(xs);

    auto issue_copy = [&](int c, int buf) {
        const float4* xv = (const float4*)x;
        unsigned dst0 = xs_base + buf * (G1_XBUF * 4);
#pragma unroll
        for (int i = 0; i < 16; i++) {
            int idx = tid + G1_THR * i;
            int r = idx >> 3, q = idx & 7;
            int gr = row0 + r; if (gr >= NN) gr = NN - 1;
            cp_async16(dst0 + (r * G1_XST + 4 * q) * 4,
                       xv + (long)gr * 128 + c * (G1_KC / 4) + q);
        }
        cp_commit();
    };

    issue_copy(0, 0);

    unsigned long long accA[8], accB[8];
#pragma unroll
    for (int p = 0; p < 8; p++) { accA[p] = 0ULL; accB[p] = 0ULL; }

    for (int c = 0; c < G1_NCH; c++) {
        if (c + 1 < G1_NCH) { issue_copy(c + 1, (c + 1) & 1); cp_wait<1>(); }
        else                { cp_wait<0>(); }
        __syncthreads();

        const float* xrA = xs + (c & 1) * G1_XBUF + tid * G1_XST;
        const float* xrB = xrA + G1_THR * G1_XST;
        const float* wk  = ws + c * G1_KC * 16;
#pragma unroll
        for (int k = 0; k < G1_KC; k += 4) {
            float4 a4 = *(const float4*)(xrA + k);
            float4 b4 = *(const float4*)(xrB + k);
            float ak[4] = {a4.x, a4.y, a4.z, a4.w};
            float bk[4] = {b4.x, b4.y, b4.z, b4.w};
#pragma unroll
            for (int kk = 0; kk < 4; kk++) {
                unsigned long long xa, xb;
                asm("mov.b64 %0,{%1,%1};" : "=l"(xa) : "f"(ak[kk]));
                asm("mov.b64 %0,{%1,%1};" : "=l"(xb) : "f"(bk[kk]));
                const ulonglong2* wv = (const ulonglong2*)(wk + (k + kk) * 16);
#pragma unroll
                for (int q = 0; q < 4; q++) {
                    ulonglong2 w2 = wv[q];
                    asm("fma.rn.f32x2 %0, %1, %2, %0;" : "+l"(accA[2*q])   : "l"(xa), "l"(w2.x));
                    asm("fma.rn.f32x2 %0, %1, %2, %0;" : "+l"(accA[2*q+1]) : "l"(xa), "l"(w2.y));
                    asm("fma.rn.f32x2 %0, %1, %2, %0;" : "+l"(accB[2*q])   : "l"(xb), "l"(w2.x));
                    asm("fma.rn.f32x2 %0, %1, %2, %0;" : "+l"(accB[2*q+1]) : "l"(xb), "l"(w2.y));
                }
            }
        }
        __syncthreads();
    }

    if (rA < NN) {
        float di = g_dinv[rA];
        float o[16];
#pragma unroll
        for (int p = 0; p < 8; p++) {
            float a0, a1;
            asm("mov.b64 {%0,%1}, %2;" : "=f"(a0), "=f"(a1) : "l"(accA[p]));
            o[2*p] = a0 * di; o[2*p+1] = a1 * di;
        }
        float4* ov = (float4*)(g_h1s + (long)rA * 16);
#pragma unroll
        for (int q = 0; q < 4; q++)
            ov[q] = make_float4(o[4*q], o[4*q+1], o[4*q+2], o[4*q+3]);
    }
    if (rB < NN) {
        float di = g_dinv[rB];
        float o[16];
#pragma unroll
        for (int p = 0; p < 8; p++) {
            float a0, a1;
            asm("mov.b64 {%0,%1}, %2;" : "=f"(a0), "=f"(a1) : "l"(accB[p]));
            o[2*p] = a0 * di; o[2*p+1] = a1 * di;
        }
        float4* ov = (float4*)(g_h1s + (long)rB * 16);
#pragma unroll
        for (int q = 0; q < 4; q++)
            ov[q] = make_float4(o[4*q], o[4*q+1], o[4*q+2], o[4*q+3]);
    }
}

// ---------------- gather1 (+fused post1), 8 lanes per node -----------------
// lane l of a group owns cols {2l, 2l+1}. Per edge the group reads one
// contiguous 64B row of h1s (1 L1tex wavefront). Indices are read coalesced
// (8 consecutive per group) and broadcast with width-8 shuffles.
__global__ __launch_bounds__(256) void gather1_kernel(const float* __restrict__ b1,
                                                      const float* __restrict__ W2) {
    __shared__ float w2s[112];
    __shared__ float b1s[16];
    __shared__ float ts[G_NPB][18];   // padded stride
    int tid = threadIdx.x;
    if (tid < 112) w2s[tid] = W2[tid];
    if (tid < 16)  b1s[tid] = b1[tid];
    __syncthreads();

    int g = tid >> 3, l = tid & 7;
    int lane = tid & 31;
    unsigned gmask = 0xFFu << (lane & ~7);
    int i = blockIdx.x * G_NPB + g;
    bool valid = (i < NN);

    int beg = 0, end = 0;
    if (valid) { beg = g_off[i]; end = g_off[i + 1]; }

    float ax = 0.0f, ay = 0.0f;
    for (int c = beg; c < end; c += 8) {
        int j = c + l;
        int idx = (j < end) ? __ldg(&g_csr_src[j]) : 0;
#pragma unroll
        for (int t = 0; t < 8; t++) {
            int s = __shfl_sync(gmask, idx, t, 8);
            if (c + t < end) {
                float2 v = *(const float2*)(g_h1s + (long)s * 16 + 2 * l);
                ax += v.x; ay += v.y;
            }
        }
    }

    if (valid) {
        float di = g_dinv[i];
        float2 h = *(const float2*)(g_h1s + (long)i * 16 + 2 * l);
        ts[g][2 * l]     = fmaxf(fmaf(di, ax + h.x, b1s[2 * l]),     0.0f);
        ts[g][2 * l + 1] = fmaxf(fmaf(di, ay + h.y, b1s[2 * l + 1]), 0.0f);
    }
    __syncthreads();

    if (valid) {
        float o = 0.0f;
        if (l < 7) {
            float di = g_dinv[i];
#pragma unroll
            for (int j2 = 0; j2 < 16; j2++) o = fmaf(ts[g][j2], w2s[j2 * 7 + l], o);
            o *= di;
        }
        g_h2s[(long)i * 8 + l] = o;   // lane 7 writes the 0 pad
    }
}

// ---------------- gather2 (+fused post2: log_softmax), 8 lanes per node ----
__global__ __launch_bounds__(256) void gather2_kernel(const float* __restrict__ b2,
                                                      float* __restrict__ out) {
    int tid = threadIdx.x;
    int g = tid >> 3, l = tid & 7;
    int lane = tid & 31;
    unsigned gmask = 0xFFu << (lane & ~7);
    int i = blockIdx.x * G_NPB + g;
    bool valid = (i < NN);

    int beg = 0, end = 0;
    if (valid) { beg = g_off[i]; end = g_off[i + 1]; }

    float acc = 0.0f;
    for (int c = beg; c < end; c += 8) {
        int j = c + l;
        int idx = (j < end) ? __ldg(&g_csr_src[j]) : 0;
#pragma unroll
        for (int t = 0; t < 8; t++) {
            int s = __shfl_sync(gmask, idx, t, 8);
            if (c + t < end) acc += __ldg(&g_h2s[(long)s * 8 + l]);
        }
    }

    // bias + self, then group log_softmax over lanes 0..6
    float di = valid ? g_dinv[i] : 0.0f;
    float h  = valid ? g_h2s[(long)i * 8 + l] : 0.0f;
    float o  = (l < 7) ? fmaf(di, acc + h, __ldg(b2 + l)) : -3.0e38f;

    float m = o;
#pragma unroll
    for (int d = 1; d < 8; d <<= 1) m = fmaxf(m, __shfl_xor_sync(gmask, m, d, 8));
    float e = (l < 7) ? expf(o - m) : 0.0f;
    float s = e;
#pragma unroll
    for (int d = 1; d < 8; d <<= 1) s += __shfl_xor_sync(gmask, s, d, 8);
    float lse = logf(s);

    if (valid && l < 7) out[(long)i * 7 + l] = o - m - lse;
}

// ---------------- host ------------------------------------------------------
extern "C" void kernel_launch(void* const* d_in, const int* in_sizes, int n_in,
                              void* d_out, int out_size) {
    const float* x  = (const float*)d_in[0];
    const void*  ei = d_in[1];
    const float* W1 = (const float*)d_in[2];
    const float* b1 = (const float*)d_in[3];
    const float* W2 = (const float*)d_in[4];
    const float* b2 = (const float*)d_in[5];
    float* out = (float*)d_out;

    void* pc;
    cudaGetSymbolAddress(&pc, g_cnt);
    cudaMemsetAsync(pc, 0, sizeof(int) * NN);

    detect_kernel<<<1, 256>>>((const unsigned*)ei);
    hist_kernel<<<NE / 256, 256>>>(ei);
    scanA_kernel<<<NBLK, 256>>>();
    scanB_kernel<<<1, 512>>>();
    scanC_kernel<<<NBLK, 256>>>();
    fill_kernel<<<NE / 256, 256>>>(ei);

    int smem = (512 * 16 + 2 * G1_XBUF) * sizeof(float);  // 106496 B
    cudaFuncSetAttribute(gemm1_kernel, cudaFuncAttributeMaxDynamicSharedMemorySize, smem);
    gemm1_kernel<<<(NN + G1_ROWS - 1) / G1_ROWS, G1_THR, smem>>>(x, W1);

    gather1_kernel<<<G_NBLK, 256>>>(b1, W2);
    gather2_kernel<<<G_NBLK, 256>>>(b2, out);
}

// round 10
// speedup vs baseline: 1.7007x; 1.0113x over previous
#include <cuda_runtime.h>
#include <stdint.h>
#include <math.h>

#define NN 100000
#define NE 3200000
#define NBLK 391          // ceil(NN/256)
#define G_NPB 32          // nodes per block in gather kernels (256 thr / 8)
#define G_NBLK ((NN + G_NPB - 1) / G_NPB)

// ---------------- scratch (device globals: no allocation allowed) ----------
__device__ int   g_cnt[NN];        // in-degree histogram (excl self-loop)
__device__ int   g_off[NN];        // CSR base per node (chunk-relocated)
__device__ int   g_cur[NN];        // fill cursors
__device__ int   g_total;          // bump allocator for chunk bases
__device__ int   g_csr_src[NE];    // CSR: src ids grouped by dst
__device__ float g_dinv[NN];
__device__ float g_h1s[NN * 16];   // (x@W1) * dinv[row]
__device__ float g_h2s[NN * 8];    // (relu-out @ W2) * dinv[row], padded to 8
__device__ int   g_is64;           // edge_index dtype flag

__device__ __forceinline__ void cp_async16(unsigned dst_smem, const void* src) {
    asm volatile("cp.async.cg.shared.global [%0], [%1], 16;"
                 :: "r"(dst_smem), "l"(src) : "memory");
}
__device__ __forceinline__ void cp_commit() {
    asm volatile("cp.async.commit_group;" ::: "memory");
}
template <int N>
__device__ __forceinline__ void cp_wait() {
    asm volatile("cp.async.wait_group %0;" :: "n"(N) : "memory");
}

// ---------------- dtype detection (also resets bump allocator) -------------
__global__ void detect_kernel(const unsigned* __restrict__ ei) {
    __shared__ int nz;
    int tid = threadIdx.x;
    if (tid == 0) { nz = 0; g_total = 0; }
    __syncthreads();
    unsigned v = 0;
#pragma unroll
    for (int i = 0; i < 16; i++) v |= ei[2 * (tid * 16 + i) + 1];
    if (v) nz = 1;
    __syncthreads();
    if (tid == 0) g_is64 = (nz == 0) ? 1 : 0;
}

// ---------------- histogram of dst ----------------------------------------
__global__ __launch_bounds__(256) void hist_kernel(const void* __restrict__ ei) {
    int e = blockIdx.x * 256 + threadIdx.x;
    if (e >= NE) return;
    int d;
    if (g_is64) d = (int)__ldg(((const long long*)ei) + NE + e);
    else        d = __ldg(((const int*)ei) + NE + e);
    atomicAdd(&g_cnt[d], 1);
}

// ---------------- single-pass scan + dinv ----------------------------------
// Chunk bases come from a bump allocator (node order across chunks is
// irrelevant: each node only needs a contiguous [off, off+cnt) range).
__global__ __launch_bounds__(256) void scan_kernel() {
    __shared__ int s[256];
    __shared__ int base_sh;
    int tid = threadIdx.x;
    int t = blockIdx.x * 256 + tid;
    int c = (t < NN) ? g_cnt[t] : 0;
    s[tid] = c;
    __syncthreads();
#pragma unroll
    for (int st = 1; st < 256; st <<= 1) {
        int a = (tid >= st) ? s[tid - st] : 0;
        __syncthreads();
        s[tid] += a;
        __syncthreads();
    }
    if (tid == 255) base_sh = atomicAdd(&g_total, s[255]);
    __syncthreads();
    if (t < NN) {
        int off = base_sh + s[tid] - c;   // exclusive within chunk
        g_off[t] = off;
        g_cur[t] = off;
        g_dinv[t] = rsqrtf((float)c + 1.0f);  // +1 = self loop
    }
}

// ---------------- CSR fill --------------------------------------------------
__global__ __launch_bounds__(256) void fill_kernel(const void* __restrict__ ei) {
    int e = blockIdx.x * 256 + threadIdx.x;
    if (e >= NE) return;
    int sv, d;
    if (g_is64) {
        const long long* p = (const long long*)ei;
        sv = (int)__ldg(p + e); d = (int)__ldg(p + NE + e);
    } else {
        const int* p = (const int*)ei;
        sv = __ldg(p + e); d = __ldg(p + NE + e);
    }
    int pos = atomicAdd(&g_cur[d], 1);
    g_csr_src[pos] = sv;
}

// ---------------- GEMM1: h1s = (x @ W1) * dinv ----------------------------
// KC=16 -> smem 72KB -> 3 CTAs/SM -> 391 CTAs in ONE wave, 12 warps/SM.
#define G1_THR  128
#define G1_ROWS 256
#define G1_KC   16
#define G1_NCH  (512 / G1_KC)
#define G1_XST  (G1_KC + 4)          // 20 floats
#define G1_XBUF (G1_ROWS * G1_XST)   // 5120 floats

__global__ __launch_bounds__(G1_THR) void gemm1_kernel(const float* __restrict__ x,
                                                       const float* __restrict__ W1) {
    extern __shared__ float smem[];
    float* ws = smem;                 // 8192 floats (32KB)
    float* xs = smem + 512 * 16;      // 2 * 5120 floats (40KB)
    int tid  = threadIdx.x;
    int row0 = blockIdx.x * G1_ROWS;
    int rA   = row0 + tid;
    int rB   = row0 + G1_THR + tid;

    {
        const float4* Wv = (const float4*)W1;
        float4* wsv = (float4*)ws;
#pragma unroll
        for (int i = 0; i < 16; i++) wsv[tid + G1_THR * i] = Wv[tid + G1_THR * i];
    }

    unsigned xs_base = (unsigned)__cvta_generic_to_shared(xs);

    // chunk copy: 256 rows x 4 float4 = 1024 float4; thread does 8.
    auto issue_copy = [&](int c, int buf) {
        const float4* xv = (const float4*)x;
        unsigned dst0 = xs_base + buf * (G1_XBUF * 4);
#pragma unroll
        for (int i = 0; i < 8; i++) {
            int idx = tid + G1_THR * i;
            int r = idx >> 2, q = idx & 3;
            int gr = row0 + r; if (gr >= NN) gr = NN - 1;
            cp_async16(dst0 + (r * G1_XST + 4 * q) * 4,
                       xv + (long)gr * 128 + c * (G1_KC / 4) + q);
        }
        cp_commit();
    };

    issue_copy(0, 0);

    unsigned long long accA[8], accB[8];
#pragma unroll
    for (int p = 0; p < 8; p++) { accA[p] = 0ULL; accB[p] = 0ULL; }

    for (int c = 0; c < G1_NCH; c++) {
        if (c + 1 < G1_NCH) { issue_copy(c + 1, (c + 1) & 1); cp_wait<1>(); }
        else                { cp_wait<0>(); }
        __syncthreads();

        const float* xrA = xs + (c & 1) * G1_XBUF + tid * G1_XST;
        const float* xrB = xrA + G1_THR * G1_XST;
        const float* wk  = ws + c * G1_KC * 16;
#pragma unroll
        for (int k = 0; k < G1_KC; k += 4) {
            float4 a4 = *(const float4*)(xrA + k);
            float4 b4 = *(const float4*)(xrB + k);
            float ak[4] = {a4.x, a4.y, a4.z, a4.w};
            float bk[4] = {b4.x, b4.y, b4.z, b4.w};
#pragma unroll
            for (int kk = 0; kk < 4; kk++) {
                unsigned long long xa, xb;
                asm("mov.b64 %0,{%1,%1};" : "=l"(xa) : "f"(ak[kk]));
                asm("mov.b64 %0,{%1,%1};" : "=l"(xb) : "f"(bk[kk]));
                const ulonglong2* wv = (const ulonglong2*)(wk + (k + kk) * 16);
#pragma unroll
                for (int q = 0; q < 4; q++) {
                    ulonglong2 w2 = wv[q];
                    asm("fma.rn.f32x2 %0, %1, %2, %0;" : "+l"(accA[2*q])   : "l"(xa), "l"(w2.x));
                    asm("fma.rn.f32x2 %0, %1, %2, %0;" : "+l"(accA[2*q+1]) : "l"(xa), "l"(w2.y));
                    asm("fma.rn.f32x2 %0, %1, %2, %0;" : "+l"(accB[2*q])   : "l"(xb), "l"(w2.x));
                    asm("fma.rn.f32x2 %0, %1, %2, %0;" : "+l"(accB[2*q+1]) : "l"(xb), "l"(w2.y));
                }
            }
        }
        __syncthreads();
    }

    if (rA < NN) {
        float di = g_dinv[rA];
        float o[16];
#pragma unroll
        for (int p = 0; p < 8; p++) {
            float a0, a1;
            asm("mov.b64 {%0,%1}, %2;" : "=f"(a0), "=f"(a1) : "l"(accA[p]));
            o[2*p] = a0 * di; o[2*p+1] = a1 * di;
        }
        float4* ov = (float4*)(g_h1s + (long)rA * 16);
#pragma unroll
        for (int q = 0; q < 4; q++)
            ov[q] = make_float4(o[4*q], o[4*q+1], o[4*q+2], o[4*q+3]);
    }
    if (rB < NN) {
        float di = g_dinv[rB];
        float o[16];
#pragma unroll
        for (int p = 0; p < 8; p++) {
            float a0, a1;
            asm("mov.b64 {%0,%1}, %2;" : "=f"(a0), "=f"(a1) : "l"(accB[p]));
            o[2*p] = a0 * di; o[2*p+1] = a1 * di;
        }
        float4* ov = (float4*)(g_h1s + (long)rB * 16);
#pragma unroll
        for (int q = 0; q < 4; q++)
            ov[q] = make_float4(o[4*q], o[4*q+1], o[4*q+2], o[4*q+3]);
    }
}

// ---------------- gather1 (+fused post1), 8 lanes per node -----------------
__global__ __launch_bounds__(256) void gather1_kernel(const float* __restrict__ b1,
                                                      const float* __restrict__ W2) {
    __shared__ float w2s[112];
    __shared__ float b1s[16];
    __shared__ float ts[G_NPB][18];   // padded stride
    int tid = threadIdx.x;
    if (tid < 112) w2s[tid] = W2[tid];
    if (tid < 16)  b1s[tid] = b1[tid];
    __syncthreads();

    int g = tid >> 3, l = tid & 7;
    int lane = tid & 31;
    unsigned gmask = 0xFFu << (lane & ~7);
    int i = blockIdx.x * G_NPB + g;
    bool valid = (i < NN);

    int beg = 0, end = 0;
    if (valid) { beg = g_off[i]; end = beg + g_cnt[i]; }

    float ax = 0.0f, ay = 0.0f;
    for (int c = beg; c < end; c += 8) {
        int j = c + l;
        int idx = (j < end) ? __ldg(&g_csr_src[j]) : 0;
#pragma unroll
        for (int t = 0; t < 8; t++) {
            int s = __shfl_sync(gmask, idx, t, 8);
            if (c + t < end) {
                float2 v = *(const float2*)(g_h1s + (long)s * 16 + 2 * l);
                ax += v.x; ay += v.y;
            }
        }
    }

    if (valid) {
        float di = g_dinv[i];
        float2 h = *(const float2*)(g_h1s + (long)i * 16 + 2 * l);
        ts[g][2 * l]     = fmaxf(fmaf(di, ax + h.x, b1s[2 * l]),     0.0f);
        ts[g][2 * l + 1] = fmaxf(fmaf(di, ay + h.y, b1s[2 * l + 1]), 0.0f);
    }
    __syncthreads();

    if (valid) {
        float o = 0.0f;
        if (l < 7) {
            float di = g_dinv[i];
#pragma unroll
            for (int j2 = 0; j2 < 16; j2++) o = fmaf(ts[g][j2], w2s[j2 * 7 + l], o);
            o *= di;
        }
        g_h2s[(long)i * 8 + l] = o;   // lane 7 writes the 0 pad
    }
}

// ---------------- gather2 (+fused post2: log_softmax), 8 lanes per node ----
__global__ __launch_bounds__(256) void gather2_kernel(const float* __restrict__ b2,
                                                      float* __restrict__ out) {
    int tid = threadIdx.x;
    int g = tid >> 3, l = tid & 7;
    int lane = tid & 31;
    unsigned gmask = 0xFFu << (lane & ~7);
    int i = blockIdx.x * G_NPB + g;
    bool valid = (i < NN);

    int beg = 0, end = 0;
    if (valid) { beg = g_off[i]; end = beg + g_cnt[i]; }

    float acc = 0.0f;
    for (int c = beg; c < end; c += 8) {
        int j = c + l;
        int idx = (j < end) ? __ldg(&g_csr_src[j]) : 0;
#pragma unroll
        for (int t = 0; t < 8; t++) {
            int s = __shfl_sync(gmask, idx, t, 8);
            if (c + t < end) acc += __ldg(&g_h2s[(long)s * 8 + l]);
        }
    }

    float di = valid ? g_dinv[i] : 0.0f;
    float h  = valid ? g_h2s[(long)i * 8 + l] : 0.0f;
    float o  = (l < 7) ? fmaf(di, acc + h, __ldg(b2 + l)) : -3.0e38f;

    float m = o;
#pragma unroll
    for (int d = 1; d < 8; d <<= 1) m = fmaxf(m, __shfl_xor_sync(gmask, m, d, 8));
    float e = (l < 7) ? expf(o - m) : 0.0f;
    float s = e;
#pragma unroll
    for (int d = 1; d < 8; d <<= 1) s += __shfl_xor_sync(gmask, s, d, 8);
    float lse = logf(s);

    if (valid && l < 7) out[(long)i * 7 + l] = o - m - lse;
}

// ---------------- host ------------------------------------------------------
extern "C" void kernel_launch(void* const* d_in, const int* in_sizes, int n_in,
                              void* d_out, int out_size) {
    const float* x  = (const float*)d_in[0];
    const void*  ei = d_in[1];
    const float* W1 = (const float*)d_in[2];
    const float* b1 = (const float*)d_in[3];
    const float* W2 = (const float*)d_in[4];
    const float* b2 = (const float*)d_in[5];
    float* out = (float*)d_out;

    // one-time infra (no device memory): side stream + fork/join events
    static cudaStream_t s2 = nullptr;
    static cudaEvent_t evF = nullptr, evJ = nullptr;
    if (!s2) {
        cudaStreamCreateWithFlags(&s2, cudaStreamNonBlocking);
        cudaEventCreateWithFlags(&evF, cudaEventDisableTiming);
        cudaEventCreateWithFlags(&evJ, cudaEventDisableTiming);
    }

    void* pc;
    cudaGetSymbolAddress(&pc, g_cnt);
    cudaMemsetAsync(pc, 0, sizeof(int) * NN);

    detect_kernel<<<1, 256>>>((const unsigned*)ei);
    hist_kernel<<<NE / 256, 256>>>(ei);
    scan_kernel<<<NBLK, 256>>>();

    // fork: gemm1 (needs only dinv) runs on s2, overlapping fill on stream 0
    cudaEventRecord(evF, 0);
    cudaStreamWaitEvent(s2, evF, 0);
    int smem = (512 * 16 + 2 * G1_XBUF) * sizeof(float);  // 73728 B
    cudaFuncSetAttribute(gemm1_kernel, cudaFuncAttributeMaxDynamicSharedMemorySize, smem);
    gemm1_kernel<<<(NN + G1_ROWS - 1) / G1_ROWS, G1_THR, smem, s2>>>(x, W1);
    cudaEventRecord(evJ, s2);

    fill_kernel<<<NE / 256, 256>>>(ei);

    // join: gather1 needs both h1s (s2) and CSR (stream 0)
    cudaStreamWaitEvent(0, evJ, 0);
    gather1_kernel<<<G_NBLK, 256>>>(b1, W2);
    gather2_kernel<<<G_NBLK, 256>>>(b2, out);
}

// round 11
// speedup vs baseline: 1.8051x; 1.0614x over previous
#include <cuda_runtime.h>
#include <stdint.h>
#include <math.h>

#define NN 100000
#define NE 3200000
#define NBLK 391          // ceil(NN/256)
#define G_NPB 32          // nodes per block in gather kernels (256 thr / 8)
#define G_NBLK ((NN + G_NPB - 1) / G_NPB)

// ---------------- scratch (device globals: no allocation allowed) ----------
__device__ int   g_cnt[NN];        // in-degree histogram (excl self-loop)
__device__ int   g_off[NN];        // CSR base per node (chunk-relocated)
__device__ int   g_cur[NN];        // fill cursors
__device__ int   g_total;          // bump allocator for chunk bases
__device__ int   g_csr_src[NE];    // CSR: src ids grouped by dst
__device__ float g_dinv[NN];
__device__ float g_h1s[NN * 16];   // x@W1, then scaled in-place by dinv[row]
__device__ float g_h2s[NN * 8];    // (relu-out @ W2) * dinv[row], padded to 8
__device__ int   g_is64;           // edge_index dtype flag

__device__ __forceinline__ void cp_async16(unsigned dst_smem, const void* src) {
    asm volatile("cp.async.cg.shared.global [%0], [%1], 16;"
                 :: "r"(dst_smem), "l"(src) : "memory");
}
__device__ __forceinline__ void cp_commit() {
    asm volatile("cp.async.commit_group;" ::: "memory");
}
template <int N>
__device__ __forceinline__ void cp_wait() {
    asm volatile("cp.async.wait_group %0;" :: "n"(N) : "memory");
}

// ---------------- dtype detection (also resets bump allocator) -------------
__global__ void detect_kernel(const unsigned* __restrict__ ei) {
    __shared__ int nz;
    int tid = threadIdx.x;
    if (tid == 0) { nz = 0; g_total = 0; }
    __syncthreads();
    unsigned v = 0;
#pragma unroll
    for (int i = 0; i < 16; i++) v |= ei[2 * (tid * 16 + i) + 1];
    if (v) nz = 1;
    __syncthreads();
    if (tid == 0) g_is64 = (nz == 0) ? 1 : 0;
}

// ---------------- histogram of dst (2 edges / thread) ----------------------
__global__ __launch_bounds__(256) void hist_kernel(const void* __restrict__ ei) {
    int e = (blockIdx.x * 256 + threadIdx.x) * 2;
    if (e >= NE) return;
    int d0, d1;
    if (g_is64) {
        longlong2 v = __ldg((const longlong2*)((const long long*)ei + NE + e));
        d0 = (int)v.x; d1 = (int)v.y;
    } else {
        int2 v = __ldg((const int2*)((const int*)ei + NE + e));
        d0 = v.x; d1 = v.y;
    }
    atomicAdd(&g_cnt[d0], 1);
    atomicAdd(&g_cnt[d1], 1);
}

// ---------------- single-pass scan + dinv ----------------------------------
__global__ __launch_bounds__(256) void scan_kernel() {
    __shared__ int s[256];
    __shared__ int base_sh;
    int tid = threadIdx.x;
    int t = blockIdx.x * 256 + tid;
    int c = (t < NN) ? g_cnt[t] : 0;
    s[tid] = c;
    __syncthreads();
#pragma unroll
    for (int st = 1; st < 256; st <<= 1) {
        int a = (tid >= st) ? s[tid - st] : 0;
        __syncthreads();
        s[tid] += a;
        __syncthreads();
    }
    if (tid == 255) base_sh = atomicAdd(&g_total, s[255]);
    __syncthreads();
    if (t < NN) {
        int off = base_sh + s[tid] - c;   // exclusive within chunk
        g_off[t] = off;
        g_cur[t] = off;
        g_dinv[t] = rsqrtf((float)c + 1.0f);  // +1 = self loop
    }
}

// ---------------- CSR fill (2 edges / thread) -------------------------------
__global__ __launch_bounds__(256) void fill_kernel(const void* __restrict__ ei) {
    int e = (blockIdx.x * 256 + threadIdx.x) * 2;
    if (e >= NE) return;
    int s0, s1, d0, d1;
    if (g_is64) {
        const long long* p = (const long long*)ei;
        longlong2 sv = __ldg((const longlong2*)(p + e));
        longlong2 dv = __ldg((const longlong2*)(p + NE + e));
        s0 = (int)sv.x; s1 = (int)sv.y; d0 = (int)dv.x; d1 = (int)dv.y;
    } else {
        const int* p = (const int*)ei;
        int2 sv = __ldg((const int2*)(p + e));
        int2 dv = __ldg((const int2*)(p + NE + e));
        s0 = sv.x; s1 = sv.y; d0 = dv.x; d1 = dv.y;
    }
    g_csr_src[atomicAdd(&g_cur[d0], 1)] = s0;
    g_csr_src[atomicAdd(&g_cur[d1], 1)] = s1;
}

// ---------------- GEMM1: h1s = x @ W1 (unscaled; zero dependencies) --------
#define G1_THR  128
#define G1_ROWS 256
#define G1_KC   32
#define G1_NCH  (512 / G1_KC)
#define G1_XST  (G1_KC + 4)
#define G1_XBUF (G1_ROWS * G1_XST)

__global__ __launch_bounds__(G1_THR) void gemm1_kernel(const float* __restrict__ x,
                                                       const float* __restrict__ W1) {
    extern __shared__ float smem[];
    float* ws = smem;
    float* xs = smem + 512 * 16;
    int tid  = threadIdx.x;
    int row0 = blockIdx.x * G1_ROWS;
    int rA   = row0 + tid;
    int rB   = row0 + G1_THR + tid;

    {
        const float4* Wv = (const float4*)W1;
        float4* wsv = (float4*)ws;
#pragma unroll
        for (int i = 0; i < 16; i++) wsv[tid + G1_THR * i] = Wv[tid + G1_THR * i];
    }

    unsigned xs_base = (unsigned)__cvta_generic_to_shared(xs);

    auto issue_copy = [&](int c, int buf) {
        const float4* xv = (const float4*)x;
        unsigned dst0 = xs_base + buf * (G1_XBUF * 4);
#pragma unroll
        for (int i = 0; i < 16; i++) {
            int idx = tid + G1_THR * i;
            int r = idx >> 3, q = idx & 7;
            int gr = row0 + r; if (gr >= NN) gr = NN - 1;
            cp_async16(dst0 + (r * G1_XST + 4 * q) * 4,
                       xv + (long)gr * 128 + c * (G1_KC / 4) + q);
        }
        cp_commit();
    };

    issue_copy(0, 0);

    unsigned long long accA[8], accB[8];
#pragma unroll
    for (int p = 0; p < 8; p++) { accA[p] = 0ULL; accB[p] = 0ULL; }

    for (int c = 0; c < G1_NCH; c++) {
        if (c + 1 < G1_NCH) { issue_copy(c + 1, (c + 1) & 1); cp_wait<1>(); }
        else                { cp_wait<0>(); }
        __syncthreads();

        const float* xrA = xs + (c & 1) * G1_XBUF + tid * G1_XST;
        const float* xrB = xrA + G1_THR * G1_XST;
        const float* wk  = ws + c * G1_KC * 16;
#pragma unroll
        for (int k = 0; k < G1_KC; k += 4) {
            float4 a4 = *(const float4*)(xrA + k);
            float4 b4 = *(const float4*)(xrB + k);
            float ak[4] = {a4.x, a4.y, a4.z, a4.w};
            float bk[4] = {b4.x, b4.y, b4.z, b4.w};
#pragma unroll
            for (int kk = 0; kk < 4; kk++) {
                unsigned long long xa, xb;
                asm("mov.b64 %0,{%1,%1};" : "=l"(xa) : "f"(ak[kk]));
                asm("mov.b64 %0,{%1,%1};" : "=l"(xb) : "f"(bk[kk]));
                const ulonglong2* wv = (const ulonglong2*)(wk + (k + kk) * 16);
#pragma unroll
                for (int q = 0; q < 4; q++) {
                    ulonglong2 w2 = wv[q];
                    asm("fma.rn.f32x2 %0, %1, %2, %0;" : "+l"(accA[2*q])   : "l"(xa), "l"(w2.x));
                    asm("fma.rn.f32x2 %0, %1, %2, %0;" : "+l"(accA[2*q+1]) : "l"(xa), "l"(w2.y));
                    asm("fma.rn.f32x2 %0, %1, %2, %0;" : "+l"(accB[2*q])   : "l"(xb), "l"(w2.x));
                    asm("fma.rn.f32x2 %0, %1, %2, %0;" : "+l"(accB[2*q+1]) : "l"(xb), "l"(w2.y));
                }
            }
        }
        __syncthreads();
    }

    if (rA < NN) {
        float o[16];
#pragma unroll
        for (int p = 0; p < 8; p++)
            asm("mov.b64 {%0,%1}, %2;" : "=f"(o[2*p]), "=f"(o[2*p+1]) : "l"(accA[p]));
        float4* ov = (float4*)(g_h1s + (long)rA * 16);
#pragma unroll
        for (int q = 0; q < 4; q++)
            ov[q] = make_float4(o[4*q], o[4*q+1], o[4*q+2], o[4*q+3]);
    }
    if (rB < NN) {
        float o[16];
#pragma unroll
        for (int p = 0; p < 8; p++)
            asm("mov.b64 {%0,%1}, %2;" : "=f"(o[2*p]), "=f"(o[2*p+1]) : "l"(accB[p]));
        float4* ov = (float4*)(g_h1s + (long)rB * 16);
#pragma unroll
        for (int q = 0; q < 4; q++)
            ov[q] = make_float4(o[4*q], o[4*q+1], o[4*q+2], o[4*q+3]);
    }
}

// ---------------- scale: h1s[i] *= dinv[i] (deferred from gemm1) -----------
__global__ __launch_bounds__(256) void scale_kernel() {
    int i = blockIdx.x * 256 + threadIdx.x;
    if (i >= NN) return;
    float di = g_dinv[i];
    float4* p = (float4*)(g_h1s + (long)i * 16);
#pragma unroll
    for (int q = 0; q < 4; q++) {
        float4 v = p[q];
        p[q] = make_float4(v.x * di, v.y * di, v.z * di, v.w * di);
    }
}

// ---------------- gather1 (+fused post1), 8 lanes per node -----------------
__global__ __launch_bounds__(256) void gather1_kernel(const float* __restrict__ b1,
                                                      const float* __restrict__ W2) {
    __shared__ float w2s[112];
    __shared__ float b1s[16];
    __shared__ float ts[G_NPB][18];   // padded stride
    int tid = threadIdx.x;
    if (tid < 112) w2s[tid] = W2[tid];
    if (tid < 16)  b1s[tid] = b1[tid];
    __syncthreads();

    int g = tid >> 3, l = tid & 7;
    int lane = tid & 31;
    unsigned gmask = 0xFFu << (lane & ~7);
    int i = blockIdx.x * G_NPB + g;
    bool valid = (i < NN);

    int beg = 0, end = 0;
    if (valid) { beg = g_off[i]; end = beg + g_cnt[i]; }

    float ax = 0.0f, ay = 0.0f;
    for (int c = beg; c < end; c += 8) {
        int j = c + l;
        int idx = (j < end) ? __ldg(&g_csr_src[j]) : 0;
#pragma unroll
        for (int t = 0; t < 8; t++) {
            int s = __shfl_sync(gmask, idx, t, 8);
            if (c + t < end) {
                float2 v = *(const float2*)(g_h1s + (long)s * 16 + 2 * l);
                ax += v.x; ay += v.y;
            }
        }
    }

    if (valid) {
        float di = g_dinv[i];
        float2 h = *(const float2*)(g_h1s + (long)i * 16 + 2 * l);
        ts[g][2 * l]     = fmaxf(fmaf(di, ax + h.x, b1s[2 * l]),     0.0f);
        ts[g][2 * l + 1] = fmaxf(fmaf(di, ay + h.y, b1s[2 * l + 1]), 0.0f);
    }
    __syncthreads();

    if (valid) {
        float o = 0.0f;
        if (l < 7) {
            float di = g_dinv[i];
#pragma unroll
            for (int j2 = 0; j2 < 16; j2++) o = fmaf(ts[g][j2], w2s[j2 * 7 + l], o);
            o *= di;
        }
        g_h2s[(long)i * 8 + l] = o;   // lane 7 writes the 0 pad
    }
}

// ---------------- gather2 (+fused post2: log_softmax), 8 lanes per node ----
__global__ __launch_bounds__(256) void gather2_kernel(const float* __restrict__ b2,
                                                      float* __restrict__ out) {
    int tid = threadIdx.x;
    int g = tid >> 3, l = tid & 7;
    int lane = tid & 31;
    unsigned gmask = 0xFFu << (lane & ~7);
    int i = blockIdx.x * G_NPB + g;
    bool valid = (i < NN);

    int beg = 0, end = 0;
    if (valid) { beg = g_off[i]; end = beg + g_cnt[i]; }

    float acc = 0.0f;
    for (int c = beg; c < end; c += 8) {
        int j = c + l;
        int idx = (j < end) ? __ldg(&g_csr_src[j]) : 0;
#pragma unroll
        for (int t = 0; t < 8; t++) {
            int s = __shfl_sync(gmask, idx, t, 8);
            if (c + t < end) acc += __ldg(&g_h2s[(long)s * 8 + l]);
        }
    }

    float di = valid ? g_dinv[i] : 0.0f;
    float h  = valid ? g_h2s[(long)i * 8 + l] : 0.0f;
    float o  = (l < 7) ? fmaf(di, acc + h, __ldg(b2 + l)) : -3.0e38f;

    float m = o;
#pragma unroll
    for (int d = 1; d < 8; d <<= 1) m = fmaxf(m, __shfl_xor_sync(gmask, m, d, 8));
    float e = (l < 7) ? expf(o - m) : 0.0f;
    float s = e;
#pragma unroll
    for (int d = 1; d < 8; d <<= 1) s += __shfl_xor_sync(gmask, s, d, 8);
    float lse = logf(s);

    if (valid && l < 7) out[(long)i * 7 + l] = o - m - lse;
}

// ---------------- host ------------------------------------------------------
extern "C" void kernel_launch(void* const* d_in, const int* in_sizes, int n_in,
                              void* d_out, int out_size) {
    const float* x  = (const float*)d_in[0];
    const void*  ei = d_in[1];
    const float* W1 = (const float*)d_in[2];
    const float* b1 = (const float*)d_in[3];
    const float* W2 = (const float*)d_in[4];
    const float* b2 = (const float*)d_in[5];
    float* out = (float*)d_out;

    static cudaStream_t s2 = nullptr;
    static cudaEvent_t evF = nullptr, evScan = nullptr, evJ = nullptr;
    if (!s2) {
        cudaStreamCreateWithFlags(&s2, cudaStreamNonBlocking);
        cudaEventCreateWithFlags(&evF, cudaEventDisableTiming);
        cudaEventCreateWithFlags(&evScan, cudaEventDisableTiming);
        cudaEventCreateWithFlags(&evJ, cudaEventDisableTiming);
    }

    // fork IMMEDIATELY: gemm1 has zero dependencies
    cudaEventRecord(evF, 0);
    cudaStreamWaitEvent(s2, evF, 0);
    int smem = (512 * 16 + 2 * G1_XBUF) * sizeof(float);  // 106496 B
    cudaFuncSetAttribute(gemm1_kernel, cudaFuncAttributeMaxDynamicSharedMemorySize, smem);
    gemm1_kernel<<<(NN + G1_ROWS - 1) / G1_ROWS, G1_THR, smem, s2>>>(x, W1);

    // main branch: CSR build
    void* pc;
    cudaGetSymbolAddress(&pc, g_cnt);
    cudaMemsetAsync(pc, 0, sizeof(int) * NN);
    detect_kernel<<<1, 256>>>((const unsigned*)ei);
    hist_kernel<<<NE / 512, 256>>>(ei);
    scan_kernel<<<NBLK, 256>>>();
    cudaEventRecord(evScan, 0);

    // s2: scale h1s once gemm1 AND scan are done (overlaps fill on main)
    cudaStreamWaitEvent(s2, evScan, 0);
    scale_kernel<<<NBLK, 256, 0, s2>>>();
    cudaEventRecord(evJ, s2);

    fill_kernel<<<NE / 512, 256>>>(ei);

    // join: gather1 needs scaled h1s (s2) and CSR (main)
    cudaStreamWaitEvent(0, evJ, 0);
    gather1_kernel<<<G_NBLK, 256>>>(b1, W2);
    gather2_kernel<<<G_NBLK, 256>>>(b2, out);
}

// round 12
// speedup vs baseline: 2.0263x; 1.1226x over previous
#include <cuda_runtime.h>
#include <stdint.h>
#include <math.h>

#define NN 100000
#define NE 3200000
#define NBLK 391          // ceil(NN/256)
#define G_NPB 32          // nodes per block in gather kernels (256 thr / 8)
#define G_NBLK ((NN + G_NPB - 1) / G_NPB)

// ---------------- scratch (device globals: no allocation allowed) ----------
__device__ int   g_cnt[NN];        // in-degree histogram (excl self-loop)
__device__ int   g_off[NN];        // CSR base per node (chunk-relocated)
__device__ int   g_cur[NN];        // fill cursors
__device__ int   g_total;          // bump allocator for chunk bases
__device__ int   g_csr_src[NE];    // CSR: src ids grouped by dst
__device__ float g_dinv[NN];
__device__ float g_h1s[NN * 16];   // x@W1, then scaled in-place by dinv[row]
__device__ float g_h2s[NN * 8];    // (relu-out @ W2) * dinv[row], padded to 8
__device__ int   g_is64;           // edge_index dtype flag

__device__ __forceinline__ void cp_async16(unsigned dst_smem, const void* src) {
    asm volatile("cp.async.cg.shared.global [%0], [%1], 16;"
                 :: "r"(dst_smem), "l"(src) : "memory");
}
__device__ __forceinline__ void cp_commit() {
    asm volatile("cp.async.commit_group;" ::: "memory");
}
template <int N>
__device__ __forceinline__ void cp_wait() {
    asm volatile("cp.async.wait_group %0;" :: "n"(N) : "memory");
}

// split f32 into exact tf32 high part + residual (lo captured to ~2^-23 rel)
__device__ __forceinline__ void split_tf32(float v, unsigned& hi, unsigned& lo) {
    unsigned u = __float_as_uint(v) & 0xFFFFE000u;
    hi = u;
    lo = __float_as_uint(v - __uint_as_float(u));
}

__device__ __forceinline__ void mma_tf32(float* d,
                                         unsigned a0, unsigned a1, unsigned a2, unsigned a3,
                                         unsigned b0, unsigned b1) {
    asm("mma.sync.aligned.m16n8k8.row.col.f32.tf32.tf32.f32 "
        "{%0,%1,%2,%3},{%4,%5,%6,%7},{%8,%9},{%0,%1,%2,%3};"
        : "+f"(d[0]), "+f"(d[1]), "+f"(d[2]), "+f"(d[3])
        : "r"(a0), "r"(a1), "r"(a2), "r"(a3), "r"(b0), "r"(b1));
}

// ---------------- dtype detection (also resets bump allocator) -------------
__global__ void detect_kernel(const unsigned* __restrict__ ei) {
    __shared__ int nz;
    int tid = threadIdx.x;
    if (tid == 0) { nz = 0; g_total = 0; }
    __syncthreads();
    unsigned v = 0;
#pragma unroll
    for (int i = 0; i < 16; i++) v |= ei[2 * (tid * 16 + i) + 1];
    if (v) nz = 1;
    __syncthreads();
    if (tid == 0) g_is64 = (nz == 0) ? 1 : 0;
}

// ---------------- histogram of dst (2 edges / thread) ----------------------
__global__ __launch_bounds__(256) void hist_kernel(const void* __restrict__ ei) {
    int e = (blockIdx.x * 256 + threadIdx.x) * 2;
    if (e >= NE) return;
    int d0, d1;
    if (g_is64) {
        longlong2 v = __ldg((const longlong2*)((const long long*)ei + NE + e));
        d0 = (int)v.x; d1 = (int)v.y;
    } else {
        int2 v = __ldg((const int2*)((const int*)ei + NE + e));
        d0 = v.x; d1 = v.y;
    }
    atomicAdd(&g_cnt[d0], 1);
    atomicAdd(&g_cnt[d1], 1);
}

// ---------------- single-pass scan + dinv ----------------------------------
__global__ __launch_bounds__(256) void scan_kernel() {
    __shared__ int s[256];
    __shared__ int base_sh;
    int tid = threadIdx.x;
    int t = blockIdx.x * 256 + tid;
    int c = (t < NN) ? g_cnt[t] : 0;
    s[tid] = c;
    __syncthreads();
#pragma unroll
    for (int st = 1; st < 256; st <<= 1) {
        int a = (tid >= st) ? s[tid - st] : 0;
        __syncthreads();
        s[tid] += a;
        __syncthreads();
    }
    if (tid == 255) base_sh = atomicAdd(&g_total, s[255]);
    __syncthreads();
    if (t < NN) {
        int off = base_sh + s[tid] - c;   // exclusive within chunk
        g_off[t] = off;
        g_cur[t] = off;
        g_dinv[t] = rsqrtf((float)c + 1.0f);  // +1 = self loop
    }
}

// ---------------- CSR fill (2 edges / thread) -------------------------------
__global__ __launch_bounds__(256) void fill_kernel(const void* __restrict__ ei) {
    int e = (blockIdx.x * 256 + threadIdx.x) * 2;
    if (e >= NE) return;
    int s0, s1, d0, d1;
    if (g_is64) {
        const long long* p = (const long long*)ei;
        longlong2 sv = __ldg((const longlong2*)(p + e));
        longlong2 dv = __ldg((const longlong2*)(p + NE + e));
        s0 = (int)sv.x; s1 = (int)sv.y; d0 = (int)dv.x; d1 = (int)dv.y;
    } else {
        const int* p = (const int*)ei;
        int2 sv = __ldg((const int2*)(p + e));
        int2 dv = __ldg((const int2*)(p + NE + e));
        s0 = sv.x; s1 = sv.y; d0 = dv.x; d1 = dv.y;
    }
    g_csr_src[atomicAdd(&g_cur[d0], 1)] = s0;
    g_csr_src[atomicAdd(&g_cur[d1], 1)] = s1;
}

// ---------------- GEMM1 (tensor core, tf32 3-pass): h1s = x @ W1 -----------
// 256 thr = 8 warps; warp -> 48 rows (3 m16 tiles); CTA -> 384 rows.
// x staged in KC=16 chunks (cp.async double buffer); W1 raw in smem.
#define GM_THR   256
#define GM_RPW   48
#define GM_ROWS  384
#define GM_KC    16
#define GM_NCH   (512 / GM_KC)
#define GM_XST   (GM_KC + 4)          // 20 floats: conflict-free A-frag reads
#define GM_XBUF  (GM_ROWS * GM_XST)   // 7680 floats
#define GM_GRID  ((NN + GM_ROWS - 1) / GM_ROWS)  // 261

__global__ __launch_bounds__(GM_THR) void gemm1_kernel(const float* __restrict__ x,
                                                       const float* __restrict__ W1) {
    extern __shared__ float smem[];
    float* ws = smem;                  // 512*16 floats (32KB)
    float* xs = smem + 512 * 16;       // 2 * 7680 floats (60KB)
    int tid  = threadIdx.x;
    int wq   = tid >> 5;
    int lane = tid & 31;
    int gid  = lane >> 2;              // groupID
    int tig  = lane & 3;               // threadID_in_group
    int row0 = blockIdx.x * GM_ROWS;

    // load W1 (2048 float4, 8 per thread)
    {
        const float4* Wv = (const float4*)W1;
        float4* wsv = (float4*)ws;
#pragma unroll
        for (int i = 0; i < 8; i++) wsv[tid + GM_THR * i] = Wv[tid + GM_THR * i];
    }

    unsigned xs_base = (unsigned)__cvta_generic_to_shared(xs);

    // chunk copy: 384 rows x 4 float4 = 1536 float4; thread does 6
    auto issue_copy = [&](int c, int buf) {
        const float4* xv = (const float4*)x;
        unsigned dst0 = xs_base + buf * (GM_XBUF * 4);
#pragma unroll
        for (int i = 0; i < 6; i++) {
            int idx = tid + GM_THR * i;
            int r = idx >> 2, q = idx & 3;
            int gr = row0 + r; if (gr >= NN) gr = NN - 1;
            cp_async16(dst0 + (r * GM_XST + 4 * q) * 4,
                       xv + (long)gr * 128 + c * (GM_KC / 4) + q);
        }
        cp_commit();
    };

    issue_copy(0, 0);

    float acc[3][2][4];
#pragma unroll
    for (int mt = 0; mt < 3; mt++)
#pragma unroll
        for (int nt = 0; nt < 2; nt++)
#pragma unroll
            for (int q = 0; q < 4; q++) acc[mt][nt][q] = 0.0f;

    for (int c = 0; c < GM_NCH; c++) {
        if (c + 1 < GM_NCH) { issue_copy(c + 1, (c + 1) & 1); cp_wait<1>(); }
        else                { cp_wait<0>(); }
        __syncthreads();

        const float* xb = xs + (c & 1) * GM_XBUF;
        int kbase = c * GM_KC;
#pragma unroll
        for (int ks = 0; ks < 2; ks++) {
            int krow = kbase + ks * 8;
            // B fragments (k8 x n8 per ntile), hi/lo
            unsigned bhi[2][2], blo[2][2];
#pragma unroll
            for (int nt = 0; nt < 2; nt++) {
                float w0 = ws[(krow + tig) * 16 + gid + 8 * nt];
                float w1 = ws[(krow + tig + 4) * 16 + gid + 8 * nt];
                split_tf32(w0, bhi[nt][0], blo[nt][0]);
                split_tf32(w1, bhi[nt][1], blo[nt][1]);
            }
#pragma unroll
            for (int mt = 0; mt < 3; mt++) {
                int rl = wq * GM_RPW + mt * 16 + gid;
                const float* xr = xb + rl * GM_XST + ks * 8 + tig;
                float a0 = xr[0];
                float a1 = xr[8 * GM_XST];
                float a2 = xr[4];
                float a3 = xr[8 * GM_XST + 4];
                unsigned ah0, al0, ah1, al1, ah2, al2, ah3, al3;
                split_tf32(a0, ah0, al0);
                split_tf32(a1, ah1, al1);
                split_tf32(a2, ah2, al2);
                split_tf32(a3, ah3, al3);
#pragma unroll
                for (int nt = 0; nt < 2; nt++) {
                    mma_tf32(acc[mt][nt], ah0, ah1, ah2, ah3, bhi[nt][0], bhi[nt][1]);
                    mma_tf32(acc[mt][nt], al0, al1, al2, al3, bhi[nt][0], bhi[nt][1]);
                    mma_tf32(acc[mt][nt], ah0, ah1, ah2, ah3, blo[nt][0], blo[nt][1]);
                }
            }
        }
        __syncthreads();
    }

    // epilogue: D rows = base + gid (+8), cols = 8*nt + 2*tig (+1)
#pragma unroll
    for (int mt = 0; mt < 3; mt++) {
        int r0 = row0 + wq * GM_RPW + mt * 16 + gid;
        int r1 = r0 + 8;
#pragma unroll
        for (int nt = 0; nt < 2; nt++) {
            int cb = 8 * nt + 2 * tig;
            if (r0 < NN)
                *(float2*)(g_h1s + (long)r0 * 16 + cb) = make_float2(acc[mt][nt][0], acc[mt][nt][1]);
            if (r1 < NN)
                *(float2*)(g_h1s + (long)r1 * 16 + cb) = make_float2(acc[mt][nt][2], acc[mt][nt][3]);
        }
    }
}

// ---------------- scale: h1s[i] *= dinv[i] (deferred from gemm1) -----------
__global__ __launch_bounds__(256) void scale_kernel() {
    int i = blockIdx.x * 256 + threadIdx.x;
    if (i >= NN) return;
    float di = g_dinv[i];
    float4* p = (float4*)(g_h1s + (long)i * 16);
#pragma unroll
    for (int q = 0; q < 4; q++) {
        float4 v = p[q];
        p[q] = make_float4(v.x * di, v.y * di, v.z * di, v.w * di);
    }
}

// ---------------- gather1 (+fused post1), 8 lanes per node -----------------
__global__ __launch_bounds__(256) void gather1_kernel(const float* __restrict__ b1,
                                                      const float* __restrict__ W2) {
    __shared__ float w2s[112];
    __shared__ float b1s[16];
    __shared__ float ts[G_NPB][18];   // padded stride
    int tid = threadIdx.x;
    if (tid < 112) w2s[tid] = W2[tid];
    if (tid < 16)  b1s[tid] = b1[tid];
    __syncthreads();

    int g = tid >> 3, l = tid & 7;
    int lane = tid & 31;
    unsigned gmask = 0xFFu << (lane & ~7);
    int i = blockIdx.x * G_NPB + g;
    bool valid = (i < NN);

    int beg = 0, end = 0;
    if (valid) { beg = g_off[i]; end = beg + g_cnt[i]; }

    float ax = 0.0f, ay = 0.0f;
    for (int c = beg; c < end; c += 8) {
        int j = c + l;
        int idx = (j < end) ? __ldg(&g_csr_src[j]) : 0;
#pragma unroll
        for (int t = 0; t < 8; t++) {
            int s = __shfl_sync(gmask, idx, t, 8);
            if (c + t < end) {
                float2 v = *(const float2*)(g_h1s + (long)s * 16 + 2 * l);
                ax += v.x; ay += v.y;
            }
        }
    }

    if (valid) {
        float di = g_dinv[i];
        float2 h = *(const float2*)(g_h1s + (long)i * 16 + 2 * l);
        ts[g][2 * l]     = fmaxf(fmaf(di, ax + h.x, b1s[2 * l]),     0.0f);
        ts[g][2 * l + 1] = fmaxf(fmaf(di, ay + h.y, b1s[2 * l + 1]), 0.0f);
    }
    __syncthreads();

    if (valid) {
        float o = 0.0f;
        if (l < 7) {
            float di = g_dinv[i];
#pragma unroll
            for (int j2 = 0; j2 < 16; j2++) o = fmaf(ts[g][j2], w2s[j2 * 7 + l], o);
            o *= di;
        }
        g_h2s[(long)i * 8 + l] = o;   // lane 7 writes the 0 pad
    }
}

// ---------------- gather2 (+fused post2: log_softmax), 8 lanes per node ----
__global__ __launch_bounds__(256) void gather2_kernel(const float* __restrict__ b2,
                                                      float* __restrict__ out) {
    int tid = threadIdx.x;
    int g = tid >> 3, l = tid & 7;
    int lane = tid & 31;
    unsigned gmask = 0xFFu << (lane & ~7);
    int i = blockIdx.x * G_NPB + g;
    bool valid = (i < NN);

    int beg = 0, end = 0;
    if (valid) { beg = g_off[i]; end = beg + g_cnt[i]; }

    float acc = 0.0f;
    for (int c = beg; c < end; c += 8) {
        int j = c + l;
        int idx = (j < end) ? __ldg(&g_csr_src[j]) : 0;
#pragma unroll
        for (int t = 0; t < 8; t++) {
            int s = __shfl_sync(gmask, idx, t, 8);
            if (c + t < end) acc += __ldg(&g_h2s[(long)s * 8 + l]);
        }
    }

    float di = valid ? g_dinv[i] : 0.0f;
    float h  = valid ? g_h2s[(long)i * 8 + l] : 0.0f;
    float o  = (l < 7) ? fmaf(di, acc + h, __ldg(b2 + l)) : -3.0e38f;

    float m = o;
#pragma unroll
    for (int d = 1; d < 8; d <<= 1) m = fmaxf(m, __shfl_xor_sync(gmask, m, d, 8));
    float e = (l < 7) ? expf(o - m) : 0.0f;
    float s = e;
#pragma unroll
    for (int d = 1; d < 8; d <<= 1) s += __shfl_xor_sync(gmask, s, d, 8);
    float lse = logf(s);

    if (valid && l < 7) out[(long)i * 7 + l] = o - m - lse;
}

// ---------------- host ------------------------------------------------------
extern "C" void kernel_launch(void* const* d_in, const int* in_sizes, int n_in,
                              void* d_out, int out_size) {
    const float* x  = (const float*)d_in[0];
    const void*  ei = d_in[1];
    const float* W1 = (const float*)d_in[2];
    const float* b1 = (const float*)d_in[3];
    const float* W2 = (const float*)d_in[4];
    const float* b2 = (const float*)d_in[5];
    float* out = (float*)d_out;

    static cudaStream_t s2 = nullptr;
    static cudaEvent_t evF = nullptr, evScan = nullptr, evJ = nullptr;
    if (!s2) {
        cudaStreamCreateWithFlags(&s2, cudaStreamNonBlocking);
        cudaEventCreateWithFlags(&evF, cudaEventDisableTiming);
        cudaEventCreateWithFlags(&evScan, cudaEventDisableTiming);
        cudaEventCreateWithFlags(&evJ, cudaEventDisableTiming);
    }

    // fork IMMEDIATELY: gemm1 has zero dependencies
    cudaEventRecord(evF, 0);
    cudaStreamWaitEvent(s2, evF, 0);
    int smem = (512 * 16 + 2 * GM_XBUF) * sizeof(float);  // 94208 B
    cudaFuncSetAttribute(gemm1_kernel, cudaFuncAttributeMaxDynamicSharedMemorySize, smem);
    gemm1_kernel<<<GM_GRID, GM_THR, smem, s2>>>(x, W1);

    // main branch: CSR build
    void* pc;
    cudaGetSymbolAddress(&pc, g_cnt);
    cudaMemsetAsync(pc, 0, sizeof(int) * NN);
    detect_kernel<<<1, 256>>>((const unsigned*)ei);
    hist_kernel<<<NE / 512, 256>>>(ei);
    scan_kernel<<<NBLK, 256>>>();
    cudaEventRecord(evScan, 0);

    // s2: scale h1s once gemm1 AND scan are done (overlaps fill on main)
    cudaStreamWaitEvent(s2, evScan, 0);
    scale_kernel<<<NBLK, 256, 0, s2>>>();
    cudaEventRecord(evJ, s2);

    fill_kernel<<<NE / 512, 256>>>(ei);

    // join: gather1 needs scaled h1s (s2) and CSR (main)
    cudaStreamWaitEvent(0, evJ, 0);
    gather1_kernel<<<G_NBLK, 256>>>(b1, W2);
    gather2_kernel<<<G_NBLK, 256>>>(b2, out);
}

// round 14
// speedup vs baseline: 2.0272x; 1.0004x over previous
#include <cuda_runtime.h>
#include <stdint.h>
#include <math.h>

#define NN 100000
#define NE 3200000
#define NBLK 391          // ceil(NN/256)
#define G_NPB 32          // nodes per block in gather kernels (256 thr / 8)
#define G_NBLK ((NN + G_NPB - 1) / G_NPB)

// ---------------- scratch (device globals: no allocation allowed) ----------
__device__ int   g_cnt[NN];        // in-degree histogram; re-zeroed by gather2
__device__ int   g_off[NN];        // CSR base per node (chunk-relocated)
__device__ int   g_cur[NN];        // fill cursors
__device__ int   g_total;          // bump allocator for chunk bases
__device__ int   g_csr_src[NE];    // CSR: src ids grouped by dst
__device__ float g_dinv[NN];
__device__ float g_h1s[NN * 16];   // x@W1, then scaled in-place by dinv[row]
__device__ float g_h2s[NN * 8];    // (relu-out @ W2) * dinv[row], padded to 8

__device__ __forceinline__ void cp_async16(unsigned dst_smem, const void* src) {
    asm volatile("cp.async.cg.shared.global [%0], [%1], 16;"
                 :: "r"(dst_smem), "l"(src) : "memory");
}
__device__ __forceinline__ void cp_commit() {
    asm volatile("cp.async.commit_group;" ::: "memory");
}
template <int N>
__device__ __forceinline__ void cp_wait() {
    asm volatile("cp.async.wait_group %0;" :: "n"(N) : "memory");
}

// split f32 into exact tf32 high part + residual
__device__ __forceinline__ void split_tf32(float v, unsigned& hi, unsigned& lo) {
    unsigned u = __float_as_uint(v) & 0xFFFFE000u;
    hi = u;
    lo = __float_as_uint(v - __uint_as_float(u));
}

__device__ __forceinline__ void mma_tf32(float* d,
                                         unsigned a0, unsigned a1, unsigned a2, unsigned a3,
                                         unsigned b0, unsigned b1) {
    asm("mma.sync.aligned.m16n8k8.row.col.f32.tf32.tf32.f32 "
        "{%0,%1,%2,%3},{%4,%5,%6,%7},{%8,%9},{%0,%1,%2,%3};"
        : "+f"(d[0]), "+f"(d[1]), "+f"(d[2]), "+f"(d[3])
        : "r"(a0), "r"(a1), "r"(a2), "r"(a3), "r"(b0), "r"(b1));
}

// per-warp dtype detect: high words of first 32 int64 entries all zero -> 64-bit
__device__ __forceinline__ bool detect64(const void* ei) {
    const unsigned* u = (const unsigned*)ei;
    unsigned hv = __ldg(u + 2 * (threadIdx.x & 31) + 1);
    return !__any_sync(0xFFFFFFFFu, hv != 0);
}

// ---------------- histogram of dst (4 edges / thread) ----------------------
__global__ __launch_bounds__(256) void hist_kernel(const void* __restrict__ ei) {
    if (blockIdx.x == 0 && threadIdx.x == 0) g_total = 0;  // consumed only by scan (after hist)
    bool is64 = detect64(ei);
    int e = (blockIdx.x * 256 + threadIdx.x) * 4;
    if (e >= NE) return;
    int d0, d1, d2, d3;
    if (is64) {
        const long long* p = (const long long*)ei + NE + e;
        longlong2 v0 = __ldg((const longlong2*)p);
        longlong2 v1 = __ldg((const longlong2*)(p + 2));
        d0 = (int)v0.x; d1 = (int)v0.y; d2 = (int)v1.x; d3 = (int)v1.y;
    } else {
        int4 v = __ldg((const int4*)((const int*)ei + NE + e));
        d0 = v.x; d1 = v.y; d2 = v.z; d3 = v.w;
    }
    atomicAdd(&g_cnt[d0], 1);
    atomicAdd(&g_cnt[d1], 1);
    atomicAdd(&g_cnt[d2], 1);
    atomicAdd(&g_cnt[d3], 1);
}

// ---------------- single-pass scan + dinv (warp-shuffle) --------------------
__global__ __launch_bounds__(256) void scan_kernel() {
    __shared__ int wsum[8];
    __shared__ int wbase[8];
    __shared__ int base_sh;
    int tid = threadIdx.x, wid = tid >> 5, lane = tid & 31;
    int t = blockIdx.x * 256 + tid;
    int c = (t < NN) ? g_cnt[t] : 0;

    int sc = c;                                   // inclusive warp scan
#pragma unroll
    for (int d = 1; d < 32; d <<= 1) {
        int n = __shfl_up_sync(0xFFFFFFFFu, sc, d);
        if (lane >= d) sc += n;
    }
    if (lane == 31) wsum[wid] = sc;
    __syncthreads();
    if (wid == 0) {
        int v = (lane < 8) ? wsum[lane] : 0;
        int s = v;
#pragma unroll
        for (int d = 1; d < 8; d <<= 1) {
            int n = __shfl_up_sync(0xFFFFFFFFu, s, d);
            if (lane >= d) s += n;
        }
        if (lane < 8) wbase[lane] = s - v;        // exclusive
        if (lane == 7) base_sh = atomicAdd(&g_total, s);
    }
    __syncthreads();
    if (t < NN) {
        int off = base_sh + wbase[wid] + sc - c;  // exclusive within chunk
        g_off[t] = off;
        g_cur[t] = off;
        g_dinv[t] = rsqrtf((float)c + 1.0f);      // +1 = self loop
    }
}

// ---------------- CSR fill (4 edges / thread) -------------------------------
__global__ __launch_bounds__(256) void fill_kernel(const void* __restrict__ ei) {
    bool is64 = detect64(ei);
    int e = (blockIdx.x * 256 + threadIdx.x) * 4;
    if (e >= NE) return;
    int s0, s1, s2, s3, d0, d1, d2, d3;
    if (is64) {
        const long long* p = (const long long*)ei;
        longlong2 a0 = __ldg((const longlong2*)(p + e));
        longlong2 a1 = __ldg((const longlong2*)(p + e + 2));
        longlong2 b0 = __ldg((const longlong2*)(p + NE + e));
        longlong2 b1 = __ldg((const longlong2*)(p + NE + e + 2));
        s0 = (int)a0.x; s1 = (int)a0.y; s2 = (int)a1.x; s3 = (int)a1.y;
        d0 = (int)b0.x; d1 = (int)b0.y; d2 = (int)b1.x; d3 = (int)b1.y;
    } else {
        const int* p = (const int*)ei;
        int4 a = __ldg((const int4*)(p + e));
        int4 b = __ldg((const int4*)(p + NE + e));
        s0 = a.x; s1 = a.y; s2 = a.z; s3 = a.w;
        d0 = b.x; d1 = b.y; d2 = b.z; d3 = b.w;
    }
    g_csr_src[atomicAdd(&g_cur[d0], 1)] = s0;
    g_csr_src[atomicAdd(&g_cur[d1], 1)] = s1;
    g_csr_src[atomicAdd(&g_cur[d2], 1)] = s2;
    g_csr_src[atomicAdd(&g_cur[d3], 1)] = s3;
}

// ---------------- GEMM1 (tensor core, tf32 3-pass): h1s = x @ W1 -----------
#define GM_THR   256
#define GM_RPW   48
#define GM_ROWS  384
#define GM_KC    16
#define GM_NCH   (512 / GM_KC)
#define GM_XST   (GM_KC + 4)
#define GM_XBUF  (GM_ROWS * GM_XST)
#define GM_GRID  ((NN + GM_ROWS - 1) / GM_ROWS)

__global__ __launch_bounds__(GM_THR) void gemm1_kernel(const float* __restrict__ x,
                                                       const float* __restrict__ W1) {
    extern __shared__ float smem[];
    float* ws = smem;
    float* xs = smem + 512 * 16;
    int tid  = threadIdx.x;
    int wq   = tid >> 5;
    int lane = tid & 31;
    int gid  = lane >> 2;
    int tig  = lane & 3;
    int row0 = blockIdx.x * GM_ROWS;

    {
        const float4* Wv = (const float4*)W1;
        float4* wsv = (float4*)ws;
#pragma unroll
        for (int i = 0; i < 8; i++) wsv[tid + GM_THR * i] = Wv[tid + GM_THR * i];
    }

    unsigned xs_base = (unsigned)__cvta_generic_to_shared(xs);

    auto issue_copy = [&](int c, int buf) {
        const float4* xv = (const float4*)x;
        unsigned dst0 = xs_base + buf * (GM_XBUF * 4);
#pragma unroll
        for (int i = 0; i < 6; i++) {
            int idx = tid + GM_THR * i;
            int r = idx >> 2, q = idx & 3;
            int gr = row0 + r; if (gr >= NN) gr = NN - 1;
            cp_async16(dst0 + (r * GM_XST + 4 * q) * 4,
                       xv + (long)gr * 128 + c * (GM_KC / 4) + q);
        }
        cp_commit();
    };

    issue_copy(0, 0);

    float acc[3][2][4];
#pragma unroll
    for (int mt = 0; mt < 3; mt++)
#pragma unroll
        for (int nt = 0; nt < 2; nt++)
#pragma unroll
            for (int q = 0; q < 4; q++) acc[mt][nt][q] = 0.0f;

    for (int c = 0; c < GM_NCH; c++) {
        if (c + 1 < GM_NCH) { issue_copy(c + 1, (c + 1) & 1); cp_wait<1>(); }
        else                { cp_wait<0>(); }
        __syncthreads();

        const float* xb = xs + (c & 1) * GM_XBUF;
        int kbase = c * GM_KC;
#pragma unroll
        for (int ks = 0; ks < 2; ks++) {
            int krow = kbase + ks * 8;
            unsigned bhi[2][2], blo[2][2];
#pragma unroll
            for (int nt = 0; nt < 2; nt++) {
                float w0 = ws[(krow + tig) * 16 + gid + 8 * nt];
                float w1 = ws[(krow + tig + 4) * 16 + gid + 8 * nt];
                split_tf32(w0, bhi[nt][0], blo[nt][0]);
                split_tf32(w1, bhi[nt][1], blo[nt][1]);
            }
#pragma unroll
            for (int mt = 0; mt < 3; mt++) {
                int rl = wq * GM_RPW + mt * 16 + gid;
                const float* xr = xb + rl * GM_XST + ks * 8 + tig;
                float a0 = xr[0];
                float a1 = xr[8 * GM_XST];
                float a2 = xr[4];
                float a3 = xr[8 * GM_XST + 4];
                unsigned ah0, al0, ah1, al1, ah2, al2, ah3, al3;
                split_tf32(a0, ah0, al0);
                split_tf32(a1, ah1, al1);
                split_tf32(a2, ah2, al2);
                split_tf32(a3, ah3, al3);
#pragma unroll
                for (int nt = 0; nt < 2; nt++) {
                    mma_tf32(acc[mt][nt], ah0, ah1, ah2, ah3, bhi[nt][0], bhi[nt][1]);
                    mma_tf32(acc[mt][nt], al0, al1, al2, al3, bhi[nt][0], bhi[nt][1]);
                    mma_tf32(acc[mt][nt], ah0, ah1, ah2, ah3, blo[nt][0], blo[nt][1]);
                }
            }
        }
        __syncthreads();
    }

#pragma unroll
    for (int mt = 0; mt < 3; mt++) {
        int r0 = row0 + wq * GM_RPW + mt * 16 + gid;
        int r1 = r0 + 8;
#pragma unroll
        for (int nt = 0; nt < 2; nt++) {
            int cb = 8 * nt + 2 * tig;
            if (r0 < NN)
                *(float2*)(g_h1s + (long)r0 * 16 + cb) = make_float2(acc[mt][nt][0], acc[mt][nt][1]);
            if (r1 < NN)
                *(float2*)(g_h1s + (long)r1 * 16 + cb) = make_float2(acc[mt][nt][2], acc[mt][nt][3]);
        }
    }
}

// ---------------- scale: h1s[i] *= dinv[i] ---------------------------------
__global__ __launch_bounds__(256) void scale_kernel() {
    int i = blockIdx.x * 256 + threadIdx.x;
    if (i >= NN) return;
    float di = g_dinv[i];
    float4* p = (float4*)(g_h1s + (long)i * 16);
#pragma unroll
    for (int q = 0; q < 4; q++) {
        float4 v = p[q];
        p[q] = make_float4(v.x * di, v.y * di, v.z * di, v.w * di);
    }
}

// ---------------- gather1 (+fused post1), 8 lanes per node -----------------
__global__ __launch_bounds__(256) void gather1_kernel(const float* __restrict__ b1,
                                                      const float* __restrict__ W2) {
    __shared__ float w2s[112];
    __shared__ float b1s[16];
    __shared__ float ts[G_NPB][18];
    int tid = threadIdx.x;
    if (tid < 112) w2s[tid] = W2[tid];
    if (tid < 16)  b1s[tid] = b1[tid];
    __syncthreads();

    int g = tid >> 3, l = tid & 7;
    int lane = tid & 31;
    unsigned gmask = 0xFFu << (lane & ~7);
    int i = blockIdx.x * G_NPB + g;
    bool valid = (i < NN);

    int beg = 0, deg = 0;
    if (valid) { beg = g_off[i]; deg = g_cnt[i]; }
    int cend = beg + (deg & ~7);
    int rem  = deg & 7;

    float ax = 0.0f, ay = 0.0f;
    for (int c = beg; c < cend; c += 8) {
        int idx = __ldg(&g_csr_src[c + l]);
#pragma unroll
        for (int t = 0; t < 8; t++) {
            int s = __shfl_sync(gmask, idx, t, 8);
            float2 v = *(const float2*)(g_h1s + (long)s * 16 + 2 * l);
            ax += v.x; ay += v.y;
        }
    }
    if (rem) {
        int idx = (l < rem) ? __ldg(&g_csr_src[cend + l]) : 0;
#pragma unroll
        for (int t = 0; t < 8; t++) {
            int s = __shfl_sync(gmask, idx, t, 8);
            if (t < rem) {
                float2 v = *(const float2*)(g_h1s + (long)s * 16 + 2 * l);
                ax += v.x; ay += v.y;
            }
        }
    }

    if (valid) {
        float di = g_dinv[i];
        float2 h = *(const float2*)(g_h1s + (long)i * 16 + 2 * l);
        ts[g][2 * l]     = fmaxf(fmaf(di, ax + h.x, b1s[2 * l]),     0.0f);
        ts[g][2 * l + 1] = fmaxf(fmaf(di, ay + h.y, b1s[2 * l + 1]), 0.0f);
    }
    __syncthreads();

    if (valid) {
        float o = 0.0f;
        if (l < 7) {
            float di = g_dinv[i];
#pragma unroll
            for (int j2 = 0; j2 < 16; j2++) o = fmaf(ts[g][j2], w2s[j2 * 7 + l], o);
            o *= di;
        }
        g_h2s[(long)i * 8 + l] = o;   // lane 7 writes the 0 pad
    }
}

// ---------------- gather2 (+fused post2: log_softmax), 8 lanes per node ----
// Also re-zeroes g_cnt[i] (replaces the host memset for the next replay).
__global__ __launch_bounds__(256) void gather2_kernel(const float* __restrict__ b2,
                                                      float* __restrict__ out) {
    int tid = threadIdx.x;
    int g = tid >> 3, l = tid & 7;
    int lane = tid & 31;
    unsigned gmask = 0xFFu << (lane & ~7);
    int i = blockIdx.x * G_NPB + g;
    bool valid = (i < NN);

    int beg = 0, deg = 0;
    if (valid) { beg = g_off[i]; deg = g_cnt[i]; }
    int cend = beg + (deg & ~7);
    int rem  = deg & 7;

    float acc = 0.0f;
    for (int c = beg; c < cend; c += 8) {
        int idx = __ldg(&g_csr_src[c + l]);
#pragma unroll
        for (int t = 0; t < 8; t++) {
            int s = __shfl_sync(gmask, idx, t, 8);
            acc += __ldg(&g_h2s[(long)s * 8 + l]);
        }
    }
    if (rem) {
        int idx = (l < rem) ? __ldg(&g_csr_src[cend + l]) : 0;
#pragma unroll
        for (int t = 0; t < 8; t++) {
            int s = __shfl_sync(gmask, idx, t, 8);
            if (t < rem) acc += __ldg(&g_h2s[(long)s * 8 + l]);
        }
    }

    if (valid && l == 0) g_cnt[i] = 0;   // restore invariant for next call

    float di = valid ? g_dinv[i] : 0.0f;
    float h  = valid ? g_h2s[(long)i * 8 + l] : 0.0f;
    float o  = (l < 7) ? fmaf(di, acc + h, __ldg(b2 + l)) : -3.0e38f;

    float m = o;
#pragma unroll
    for (int d = 1; d < 8; d <<= 1) m = fmaxf(m, __shfl_xor_sync(gmask, m, d, 8));
    float e = (l < 7) ? expf(o - m) : 0.0f;
    float s = e;
#pragma unroll
    for (int d = 1; d < 8; d <<= 1) s += __shfl_xor_sync(gmask, s, d, 8);
    float lse = logf(s);

    if (valid && l < 7) out[(long)i * 7 + l] = o - m - lse;
}

// ---------------- host ------------------------------------------------------
extern "C" void kernel_launch(void* const* d_in, const int* in_sizes, int n_in,
                              void* d_out, int out_size) {
    const float* x  = (const float*)d_in[0];
    const void*  ei = d_in[1];
    const float* W1 = (const float*)d_in[2];
    const float* b1 = (const float*)d_in[3];
    const float* W2 = (const float*)d_in[4];
    const float* b2 = (const float*)d_in[5];
    float* out = (float*)d_out;

    static cudaStream_t s2 = nullptr;
    static cudaEvent_t evF = nullptr, evScan = nullptr, evJ = nullptr;
    if (!s2) {
        cudaStreamCreateWithFlags(&s2, cudaStreamNonBlocking);
        cudaEventCreateWithFlags(&evF, cudaEventDisableTiming);
        cudaEventCreateWithFlags(&evScan, cudaEventDisableTiming);
        cudaEventCreateWithFlags(&evJ, cudaEventDisableTiming);
    }

    // fork IMMEDIATELY: gemm1 has zero dependencies
    cudaEventRecord(evF, 0);
    cudaStreamWaitEvent(s2, evF, 0);
    int smem = (512 * 16 + 2 * GM_XBUF) * sizeof(float);  // 94208 B
    cudaFuncSetAttribute(gemm1_kernel, cudaFuncAttributeMaxDynamicSharedMemorySize, smem);
    gemm1_kernel<<<GM_GRID, GM_THR, smem, s2>>>(x, W1);

    // main branch: CSR build (g_cnt arrives zeroed from previous call / init)
    hist_kernel<<<NE / 1024, 256>>>(ei);
    scan_kernel<<<NBLK, 256>>>();
    cudaEventRecord(evScan, 0);

    // s2: scale h1s once gemm1 AND scan are done (overlaps fill on main)
    cudaStreamWaitEvent(s2, evScan, 0);
    scale_kernel<<<NBLK, 256, 0, s2>>>();
    cudaEventRecord(evJ, s2);

    fill_kernel<<<NE / 1024, 256>>>(ei);

    // join: gather1 needs scaled h1s (s2) and CSR (main)
    cudaStreamWaitEvent(0, evJ, 0);
    gather1_kernel<<<G_NBLK, 256>>>(b1, W2);
    gather2_kernel<<<G_NBLK, 256>>>(b2, out);
}